// round 9
// baseline (speedup 1.0000x reference)
#include <cuda_runtime.h>
#include <cuda_bf16.h>
#include <cuda_fp16.h>
#include <cstdint>

#define NB 4
#define NC 256
#define NHW 4096
#define KT 32
#define SP 40    // padded smem row stride (bf16 elems) for conv kernels
#define KTG 64   // gemm1/gemm2 k-tile
#define SPG 72   // padded row stride for KTG tiles (144B, conflict-free)

// ---------------- scratch ----------------
__device__ __nv_bfloat16 g_hT_hi[NB*NHW*NC];
__device__ __nv_bfloat16 g_hT_lo[NB*NHW*NC];
__device__ __nv_bfloat16 g_w_hi[4*NC*NC];   // q,k,v,proj
__device__ __nv_bfloat16 g_w_lo[4*NC*NC];
__device__ __nv_bfloat16 g_q[NB*NHW*NC];    // quantized q codes [b][n][c]
__device__ __nv_bfloat16 g_k[NB*NHW*NC];    // quantized k codes [b][m][c]
__device__ __nv_bfloat16 g_v[NB*NC*NHW];    // quantized v codes [b][c][m]
__device__ __half        g_S[(size_t)NB*NHW*NHW];  // logits (f16)
__device__ __nv_bfloat16 g_a[(size_t)NB*NHW*NHW];  // quantized attn codes [b][n][m]
__device__ __nv_bfloat16 g_hoT_hi[NB*NHW*NC];
__device__ __nv_bfloat16 g_hoT_lo[NB*NHW*NC];

// ---------------- helpers ----------------
__device__ __forceinline__ void mma16816(float d[4], const uint32_t a[4], const uint32_t b[2]) {
    asm volatile(
        "mma.sync.aligned.m16n8k16.row.col.f32.bf16.bf16.f32 "
        "{%0,%1,%2,%3},{%4,%5,%6,%7},{%8,%9},{%0,%1,%2,%3};\n"
        : "+f"(d[0]), "+f"(d[1]), "+f"(d[2]), "+f"(d[3])
        : "r"(a[0]), "r"(a[1]), "r"(a[2]), "r"(a[3]), "r"(b[0]), "r"(b[1]));
}
__device__ __forceinline__ void ldsm4(uint32_t r[4], const void* p) {
    uint32_t a = (uint32_t)__cvta_generic_to_shared(p);
    asm volatile("ldmatrix.sync.aligned.m8n8.x4.shared.b16 {%0,%1,%2,%3},[%4];\n"
        : "=r"(r[0]), "=r"(r[1]), "=r"(r[2]), "=r"(r[3]) : "r"(a));
}
__device__ __forceinline__ void cp16(void* s, const void* g) {
    uint32_t sa = (uint32_t)__cvta_generic_to_shared(s);
    asm volatile("cp.async.cg.shared.global [%0],[%1],16;\n" :: "r"(sa), "l"(g));
}
#define CP_COMMIT() asm volatile("cp.async.commit_group;\n")
#define CP_WAIT0()  asm volatile("cp.async.wait_group 0;\n")
#define CP_WAIT1()  asm volatile("cp.async.wait_group 1;\n")

__device__ __forceinline__ float fq_code(float v, float dinv, float zp) {
    float q = rintf(v * dinv) + zp;
    q = fminf(fmaxf(q, 0.0f), 255.0f);
    return q - zp;
}

// ---------------- 1) GroupNorm -> hT hi/lo [b][n][c] ----------------
__global__ void __launch_bounds__(256) gn_kernel(const float* __restrict__ x,
                                                 const float* __restrict__ gam,
                                                 const float* __restrict__ bet) {
    int b = blockIdx.x >> 5, gr = blockIdx.x & 31;
    const float* xp = x + ((size_t)(b * NC) + gr * 8) * NHW;
    int tid = threadIdx.x;
    const int Nf4 = 8 * NHW / 4;
    const float4* x4 = (const float4*)xp;
    float s = 0.f, ss = 0.f;
    for (int i = tid; i < Nf4; i += 256) {
        float4 v = x4[i];
        s  += v.x + v.y + v.z + v.w;
        ss += v.x * v.x + v.y * v.y + v.z * v.z + v.w * v.w;
    }
    __shared__ float rs[8], rss[8], s_sc[8], s_sh[8];
    #pragma unroll
    for (int o = 16; o; o >>= 1) {
        s  += __shfl_down_sync(0xffffffffu, s, o);
        ss += __shfl_down_sync(0xffffffffu, ss, o);
    }
    if ((tid & 31) == 0) { rs[tid >> 5] = s; rss[tid >> 5] = ss; }
    __syncthreads();
    float ts = 0.f, tss = 0.f;
    #pragma unroll
    for (int k = 0; k < 8; k++) { ts += rs[k]; tss += rss[k]; }
    const float inv = 1.0f / (float)(8 * NHW);
    float mu = ts * inv;
    float var = tss * inv - mu * mu;
    float rstd = 1.0f / sqrtf(var + 1e-6f);
    if (tid < 8) {
        float gm = gam[gr * 8 + tid];
        s_sc[tid] = gm * rstd;
        s_sh[tid] = bet[gr * 8 + tid] - mu * gm * rstd;
    }
    __syncthreads();
    __nv_bfloat16* Hh = g_hT_hi + (size_t)b * NHW * NC + gr * 8;
    __nv_bfloat16* Hl = g_hT_lo + (size_t)b * NHW * NC + gr * 8;
    for (int n = tid; n < NHW; n += 256) {
        union { __nv_bfloat16 h[8]; uint4 u; } ph, pl;
        #pragma unroll
        for (int c = 0; c < 8; c++) {
            float v = xp[(size_t)c * NHW + n] * s_sc[c] + s_sh[c];
            __nv_bfloat16 hi = __float2bfloat16(v);
            ph.h[c] = hi;
            pl.h[c] = __float2bfloat16(v - __bfloat162float(hi));
        }
        *(uint4*)&Hh[(size_t)n * NC] = ph.u;
        *(uint4*)&Hl[(size_t)n * NC] = pl.u;
    }
}

// ---------------- 2) weight split ----------------
__global__ void __launch_bounds__(256) wsplit_kernel(const float* __restrict__ wq,
                                                     const float* __restrict__ wk,
                                                     const float* __restrict__ wv,
                                                     const float* __restrict__ wp) {
    int idx = blockIdx.x * 256 + threadIdx.x;
    const float* ws[4] = {wq, wk, wv, wp};
    #pragma unroll
    for (int m = 0; m < 4; m++) {
        float v = ws[m][idx];
        __nv_bfloat16 hi = __float2bfloat16(v);
        g_w_hi[m * NC * NC + idx] = hi;
        g_w_lo[m * NC * NC + idx] = __float2bfloat16(v - __bfloat162float(hi));
    }
}

// ---------------- 3) QKV: split-bf16 mma conv + quantize (ldmatrix) ----------------
__global__ void __launch_bounds__(256) qkv_kernel(
    const float* __restrict__ bq, const float* __restrict__ bk, const float* __restrict__ bv,
    const float* __restrict__ dqp, const float* __restrict__ zqp,
    const float* __restrict__ dkp, const float* __restrict__ zkp,
    const float* __restrict__ dvp, const float* __restrict__ zvp) {
    int z = blockIdx.z;
    int b = z / 3, which = z - b * 3;
    const __nv_bfloat16* Wh = g_w_hi + which * NC * NC;
    const __nv_bfloat16* Wl = g_w_lo + which * NC * NC;
    const float* bias;
    float d, zp;
    if (which == 0)      { bias = bq; d = dqp[0]; zp = zqp[0]; }
    else if (which == 1) { bias = bk; d = dkp[0]; zp = zkp[0]; }
    else                 { bias = bv; d = dvp[0]; zp = zvp[0]; }
    int n0 = blockIdx.x * 128, o0 = blockIdx.y * 128;
    const __nv_bfloat16* Ahg = g_hT_hi + (size_t)b * NHW * NC;
    const __nv_bfloat16* Alg = g_hT_lo + (size_t)b * NHW * NC;

    __shared__ union SmU {
        struct { __nv_bfloat16 Ah[128][SP], Al[128][SP], Bh[128][SP], Bl[128][SP]; } m;
        __nv_bfloat16 tb[128][136];
    } sm;

    int tid = threadIdx.x, warp = tid >> 5, lane = tid & 31;
    int g = lane >> 2, ti = lane & 3, wr = warp & 1, wc = warp >> 1;
    int la  = lane & 15;
    int kA  = ((lane >> 4) & 1) * 8;
    int lb  = (lane & 7) + ((lane >> 4) & 1) * 8;
    int kB  = ((lane >> 3) & 1) * 8;
    float acc[4][4][4] = {};

    for (int k0 = 0; k0 < NC; k0 += KT) {
        #pragma unroll
        for (int u = 0; u < 2; u++) {
            int c = tid + u * 256; int r = c >> 2, q = (c & 3) * 8;
            cp16(&sm.m.Ah[r][q], &Ahg[(size_t)(n0 + r) * NC + k0 + q]);
            cp16(&sm.m.Al[r][q], &Alg[(size_t)(n0 + r) * NC + k0 + q]);
            cp16(&sm.m.Bh[r][q], &Wh[(o0 + r) * NC + k0 + q]);
            cp16(&sm.m.Bl[r][q], &Wl[(o0 + r) * NC + k0 + q]);
        }
        CP_COMMIT(); CP_WAIT0();
        __syncthreads();
        #pragma unroll
        for (int kk = 0; kk < KT; kk += 16) {
            uint32_t ah[4][4], al[4][4], bh[2][4], bl[2][4];
            #pragma unroll
            for (int mi = 0; mi < 4; mi++) {
                int r = wr * 64 + mi * 16 + la;
                ldsm4(ah[mi], &sm.m.Ah[r][kk + kA]);
                ldsm4(al[mi], &sm.m.Al[r][kk + kA]);
            }
            #pragma unroll
            for (int nj = 0; nj < 2; nj++) {
                int c = wc * 32 + nj * 16 + lb;
                ldsm4(bh[nj], &sm.m.Bh[c][kk + kB]);
                ldsm4(bl[nj], &sm.m.Bl[c][kk + kB]);
            }
            #pragma unroll
            for (int mi = 0; mi < 4; mi++)
                #pragma unroll
                for (int ni = 0; ni < 4; ni++) {
                    mma16816(acc[mi][ni], ah[mi], &bh[ni >> 1][(ni & 1) * 2]);
                    mma16816(acc[mi][ni], ah[mi], &bl[ni >> 1][(ni & 1) * 2]);
                    mma16816(acc[mi][ni], al[mi], &bh[ni >> 1][(ni & 1) * 2]);
                }
        }
        __syncthreads();
    }

    float dinv = 1.0f / d;
    if (which < 2) {
        __nv_bfloat16* Out = (which == 0 ? g_q : g_k) + (size_t)b * NHW * NC;
        #pragma unroll
        for (int mi = 0; mi < 4; mi++) {
            int n = n0 + wr * 64 + mi * 16 + g;
            #pragma unroll
            for (int ni = 0; ni < 4; ni++) {
                int o = o0 + wc * 32 + ni * 8 + 2 * ti;
                float b0 = bias[o], b1 = bias[o + 1];
                union { __nv_bfloat16 h[2]; uint32_t u; } p0, p1;
                p0.h[0] = __float2bfloat16(fq_code(acc[mi][ni][0] + b0, dinv, zp));
                p0.h[1] = __float2bfloat16(fq_code(acc[mi][ni][1] + b1, dinv, zp));
                p1.h[0] = __float2bfloat16(fq_code(acc[mi][ni][2] + b0, dinv, zp));
                p1.h[1] = __float2bfloat16(fq_code(acc[mi][ni][3] + b1, dinv, zp));
                *(uint32_t*)&Out[(size_t)n * NC + o]       = p0.u;
                *(uint32_t*)&Out[(size_t)(n + 8) * NC + o] = p1.u;
            }
        }
    } else {
        #pragma unroll
        for (int mi = 0; mi < 4; mi++) {
            int nl = wr * 64 + mi * 16 + g;
            #pragma unroll
            for (int ni = 0; ni < 4; ni++) {
                int ol = wc * 32 + ni * 8 + 2 * ti;
                float b0 = bias[o0 + ol], b1 = bias[o0 + ol + 1];
                sm.tb[ol    ][nl    ] = __float2bfloat16(fq_code(acc[mi][ni][0] + b0, dinv, zp));
                sm.tb[ol + 1][nl    ] = __float2bfloat16(fq_code(acc[mi][ni][1] + b1, dinv, zp));
                sm.tb[ol    ][nl + 8] = __float2bfloat16(fq_code(acc[mi][ni][2] + b0, dinv, zp));
                sm.tb[ol + 1][nl + 8] = __float2bfloat16(fq_code(acc[mi][ni][3] + b1, dinv, zp));
            }
        }
        __syncthreads();
        int r = tid >> 1, half = (tid & 1) * 64;
        #pragma unroll
        for (int j = 0; j < 64; j += 8)
            *(uint4*)&g_v[((size_t)b * NC + o0 + r) * NHW + n0 + half + j] =
                *(uint4*)&sm.tb[r][half + j];
    }
}

// ---------------- 4) gemm1: S = q . k^T (bf16 mma, KTG=64, f16 out, 3 CTAs/SM) ----------------
__global__ void __launch_bounds__(256, 3) gemm1_kernel(const float* __restrict__ dqp,
                                                       const float* __restrict__ dkp) {
    extern __shared__ __nv_bfloat16 ds[];
    __nv_bfloat16 (*As)[128][SPG] = (__nv_bfloat16 (*)[128][SPG])ds;
    __nv_bfloat16 (*Bs)[128][SPG] = (__nv_bfloat16 (*)[128][SPG])(ds + 2 * 128 * SPG);

    int b = blockIdx.z, m0 = blockIdx.x * 128, n0 = blockIdx.y * 128;
    const __nv_bfloat16* A  = g_q + (size_t)b * NHW * NC;
    const __nv_bfloat16* Bm = g_k + (size_t)b * NHW * NC;
    int tid = threadIdx.x, warp = tid >> 5, lane = tid & 31;
    int g = lane >> 2, ti = lane & 3, wr = warp & 1, wc = warp >> 1;
    int la  = lane & 15;
    int kA  = ((lane >> 4) & 1) * 8;
    int lb  = (lane & 7) + ((lane >> 4) & 1) * 8;
    int kB  = ((lane >> 3) & 1) * 8;
    float acc[4][4][4] = {};
    #pragma unroll
    for (int u = 0; u < 4; u++) {
        int c = tid + u * 256; int r = c >> 3, q = (c & 7) * 8;
        cp16(&As[0][r][q], &A [(size_t)(n0 + r) * NC + q]);
        cp16(&Bs[0][r][q], &Bm[(size_t)(m0 + r) * NC + q]);
    }
    CP_COMMIT();
    const int T = NC / KTG;   // 4
    for (int t = 0; t < T; t++) {
        if (t + 1 < T) {
            int k0 = (t + 1) * KTG, bi = (t + 1) & 1;
            #pragma unroll
            for (int u = 0; u < 4; u++) {
                int c = tid + u * 256; int r = c >> 3, q = (c & 7) * 8;
                cp16(&As[bi][r][q], &A [(size_t)(n0 + r) * NC + k0 + q]);
                cp16(&Bs[bi][r][q], &Bm[(size_t)(m0 + r) * NC + k0 + q]);
            }
            CP_COMMIT(); CP_WAIT1();
        } else CP_WAIT0();
        __syncthreads();
        int bi = t & 1;
        #pragma unroll
        for (int kk = 0; kk < KTG; kk += 16) {
            uint32_t af[4][4], bf[2][4];
            #pragma unroll
            for (int mi = 0; mi < 4; mi++)
                ldsm4(af[mi], &As[bi][wr * 64 + mi * 16 + la][kk + kA]);
            #pragma unroll
            for (int nj = 0; nj < 2; nj++)
                ldsm4(bf[nj], &Bs[bi][wc * 32 + nj * 16 + lb][kk + kB]);
            #pragma unroll
            for (int mi = 0; mi < 4; mi++)
                #pragma unroll
                for (int ni = 0; ni < 4; ni++)
                    mma16816(acc[mi][ni], af[mi], &bf[ni >> 1][(ni & 1) * 2]);
        }
        __syncthreads();
    }
    float sc = dqp[0] * dkp[0] * 0.0625f;
    __half* Sp = g_S + (size_t)b * NHW * NHW;
    #pragma unroll
    for (int mi = 0; mi < 4; mi++) {
        int n = n0 + wr * 64 + mi * 16 + g;
        #pragma unroll
        for (int ni = 0; ni < 4; ni++) {
            int m = m0 + wc * 32 + ni * 8 + 2 * ti;
            *(__half2*)&Sp[(size_t)n * NHW + m] =
                __floats2half2_rn(acc[mi][ni][0] * sc, acc[mi][ni][1] * sc);
            *(__half2*)&Sp[(size_t)(n + 8) * NHW + m] =
                __floats2half2_rn(acc[mi][ni][2] * sc, acc[mi][ni][3] * sc);
        }
    }
}

// ---------------- 5) softmax + 8-bit quantize (f16 in, bf16 codes out) ----------------
__global__ void __launch_bounds__(256) softmax_kernel(const float* __restrict__ dwp,
                                                      const float* __restrict__ zwp) {
    size_t row = blockIdx.x;
    const __half* s = g_S + row * NHW;
    __nv_bfloat16* a = g_a + row * NHW;
    int tid = threadIdx.x;
    float v[16];
    #pragma unroll
    for (int j = 0; j < 2; j++) {
        uint4 t = *(const uint4*)&s[(j * 256 + tid) * 8];
        const __half2* hp = (const __half2*)&t;
        #pragma unroll
        for (int l = 0; l < 4; l++) {
            float2 f = __half22float2(hp[l]);
            v[j * 8 + 2 * l]     = f.x;
            v[j * 8 + 2 * l + 1] = f.y;
        }
    }
    float mx = -3.4e38f;
    #pragma unroll
    for (int i = 0; i < 16; i++) mx = fmaxf(mx, v[i]);
    __shared__ float red[8];
    #pragma unroll
    for (int o = 16; o; o >>= 1) mx = fmaxf(mx, __shfl_xor_sync(0xffffffffu, mx, o));
    if ((tid & 31) == 0) red[tid >> 5] = mx;
    __syncthreads();
    mx = red[0];
    #pragma unroll
    for (int k = 1; k < 8; k++) mx = fmaxf(mx, red[k]);
    __syncthreads();
    float sum = 0.f;
    #pragma unroll
    for (int i = 0; i < 16; i++) { v[i] = __expf(v[i] - mx); sum += v[i]; }
    #pragma unroll
    for (int o = 16; o; o >>= 1) sum += __shfl_xor_sync(0xffffffffu, sum, o);
    if ((tid & 31) == 0) red[tid >> 5] = sum;
    __syncthreads();
    sum = 0.f;
    #pragma unroll
    for (int k = 0; k < 8; k++) sum += red[k];
    float rinv = 1.0f / sum;
    float dinv = 1.0f / dwp[0], zw = zwp[0];
    #pragma unroll
    for (int j = 0; j < 2; j++) {
        union { __nv_bfloat16 h[8]; uint4 u; } pk;
        #pragma unroll
        for (int l = 0; l < 8; l++)
            pk.h[l] = __float2bfloat16(fq_code(v[j * 8 + l] * rinv, dinv, zw));
        *(uint4*)&a[(j * 256 + tid) * 8] = pk.u;
    }
}

// ---------------- 6) gemm2: hoT = a . v^T, emit split hi/lo (KTG=64, 3 CTAs/SM) ----------------
__global__ void __launch_bounds__(256, 3) gemm2_kernel(const float* __restrict__ dvp,
                                                       const float* __restrict__ dwp) {
    extern __shared__ __nv_bfloat16 ds[];
    __nv_bfloat16 (*As)[128][SPG] = (__nv_bfloat16 (*)[128][SPG])ds;
    __nv_bfloat16 (*Bs)[128][SPG] = (__nv_bfloat16 (*)[128][SPG])(ds + 2 * 128 * SPG);

    int b = blockIdx.z, n0 = blockIdx.x * 128, c0 = blockIdx.y * 128;
    const __nv_bfloat16* A  = g_a + (size_t)b * NHW * NHW;   // [n][m]
    const __nv_bfloat16* Bm = g_v + (size_t)b * NC * NHW;    // [c][m]
    int tid = threadIdx.x, warp = tid >> 5, lane = tid & 31;
    int g = lane >> 2, ti = lane & 3, wr = warp & 1, wc = warp >> 1;
    int la  = lane & 15;
    int kA  = ((lane >> 4) & 1) * 8;
    int lb  = (lane & 7) + ((lane >> 4) & 1) * 8;
    int kB  = ((lane >> 3) & 1) * 8;
    float acc[4][4][4] = {};
    #pragma unroll
    for (int u = 0; u < 4; u++) {
        int c = tid + u * 256; int r = c >> 3, q = (c & 7) * 8;
        cp16(&As[0][r][q], &A [(size_t)(n0 + r) * NHW + q]);
        cp16(&Bs[0][r][q], &Bm[(size_t)(c0 + r) * NHW + q]);
    }
    CP_COMMIT();
    const int T = NHW / KTG;  // 64
    for (int t = 0; t < T; t++) {
        if (t + 1 < T) {
            int k0 = (t + 1) * KTG, bi = (t + 1) & 1;
            #pragma unroll
            for (int u = 0; u < 4; u++) {
                int c = tid + u * 256; int r = c >> 3, q = (c & 7) * 8;
                cp16(&As[bi][r][q], &A [(size_t)(n0 + r) * NHW + k0 + q]);
                cp16(&Bs[bi][r][q], &Bm[(size_t)(c0 + r) * NHW + k0 + q]);
            }
            CP_COMMIT(); CP_WAIT1();
        } else CP_WAIT0();
        __syncthreads();
        int bi = t & 1;
        #pragma unroll
        for (int kk = 0; kk < KTG; kk += 16) {
            uint32_t af[4][4], bf[2][4];
            #pragma unroll
            for (int mi = 0; mi < 4; mi++)
                ldsm4(af[mi], &As[bi][wr * 64 + mi * 16 + la][kk + kA]);
            #pragma unroll
            for (int nj = 0; nj < 2; nj++)
                ldsm4(bf[nj], &Bs[bi][wc * 32 + nj * 16 + lb][kk + kB]);
            #pragma unroll
            for (int mi = 0; mi < 4; mi++)
                #pragma unroll
                for (int ni = 0; ni < 4; ni++)
                    mma16816(acc[mi][ni], af[mi], &bf[ni >> 1][(ni & 1) * 2]);
        }
        __syncthreads();
    }
    float sc = dvp[0] * dwp[0];
    __nv_bfloat16* Oh = g_hoT_hi + (size_t)b * NHW * NC;
    __nv_bfloat16* Ol = g_hoT_lo + (size_t)b * NHW * NC;
    #pragma unroll
    for (int mi = 0; mi < 4; mi++) {
        int n = n0 + wr * 64 + mi * 16 + g;
        #pragma unroll
        for (int ni = 0; ni < 4; ni++) {
            int c = c0 + wc * 32 + ni * 8 + 2 * ti;
            #pragma unroll
            for (int half = 0; half < 2; half++) {
                float v0 = acc[mi][ni][2 * half] * sc;
                float v1 = acc[mi][ni][2 * half + 1] * sc;
                __nv_bfloat16 h0 = __float2bfloat16(v0);
                __nv_bfloat16 h1 = __float2bfloat16(v1);
                union { __nv_bfloat16 h[2]; uint32_t u; } ph, pl;
                ph.h[0] = h0; ph.h[1] = h1;
                pl.h[0] = __float2bfloat16(v0 - __bfloat162float(h0));
                pl.h[1] = __float2bfloat16(v1 - __bfloat162float(h1));
                size_t off = (size_t)(n + 8 * half) * NC + c;
                *(uint32_t*)&Oh[off] = ph.u;
                *(uint32_t*)&Ol[off] = pl.u;
            }
        }
    }
}

// ---------------- 7) proj: split-bf16 mma + bias + residual (ldmatrix) ----------------
__global__ void __launch_bounds__(256) proj_kernel(const float* __restrict__ x,
                                                   const float* __restrict__ bias,
                                                   float* __restrict__ out) {
    int b = blockIdx.z;
    int n0 = blockIdx.x * 128, o0 = blockIdx.y * 128;
    const __nv_bfloat16* Wh = g_w_hi + 3 * NC * NC;
    const __nv_bfloat16* Wl = g_w_lo + 3 * NC * NC;
    const __nv_bfloat16* Ahg = g_hoT_hi + (size_t)b * NHW * NC;
    const __nv_bfloat16* Alg = g_hoT_lo + (size_t)b * NHW * NC;

    __shared__ union SmU {
        struct { __nv_bfloat16 Ah[128][SP], Al[128][SP], Bh[128][SP], Bl[128][SP]; } m;
        float tf[64][132];
    } sm;

    int tid = threadIdx.x, warp = tid >> 5, lane = tid & 31;
    int g = lane >> 2, ti = lane & 3, wr = warp & 1, wc = warp >> 1;
    int la  = lane & 15;
    int kA  = ((lane >> 4) & 1) * 8;
    int lb  = (lane & 7) + ((lane >> 4) & 1) * 8;
    int kB  = ((lane >> 3) & 1) * 8;
    float acc[4][4][4] = {};

    for (int k0 = 0; k0 < NC; k0 += KT) {
        #pragma unroll
        for (int u = 0; u < 2; u++) {
            int c = tid + u * 256; int r = c >> 2, q = (c & 3) * 8;
            cp16(&sm.m.Ah[r][q], &Ahg[(size_t)(n0 + r) * NC + k0 + q]);
            cp16(&sm.m.Al[r][q], &Alg[(size_t)(n0 + r) * NC + k0 + q]);
            cp16(&sm.m.Bh[r][q], &Wh[(o0 + r) * NC + k0 + q]);
            cp16(&sm.m.Bl[r][q], &Wl[(o0 + r) * NC + k0 + q]);
        }
        CP_COMMIT(); CP_WAIT0();
        __syncthreads();
        #pragma unroll
        for (int kk = 0; kk < KT; kk += 16) {
            uint32_t ah[4][4], al[4][4], bh[2][4], bl[2][4];
            #pragma unroll
            for (int mi = 0; mi < 4; mi++) {
                int r = wr * 64 + mi * 16 + la;
                ldsm4(ah[mi], &sm.m.Ah[r][kk + kA]);
                ldsm4(al[mi], &sm.m.Al[r][kk + kA]);
            }
            #pragma unroll
            for (int nj = 0; nj < 2; nj++) {
                int c = wc * 32 + nj * 16 + lb;
                ldsm4(bh[nj], &sm.m.Bh[c][kk + kB]);
                ldsm4(bl[nj], &sm.m.Bl[c][kk + kB]);
            }
            #pragma unroll
            for (int mi = 0; mi < 4; mi++)
                #pragma unroll
                for (int ni = 0; ni < 4; ni++) {
                    mma16816(acc[mi][ni], ah[mi], &bh[ni >> 1][(ni & 1) * 2]);
                    mma16816(acc[mi][ni], ah[mi], &bl[ni >> 1][(ni & 1) * 2]);
                    mma16816(acc[mi][ni], al[mi], &bh[ni >> 1][(ni & 1) * 2]);
                }
        }
        __syncthreads();
    }

    #pragma unroll
    for (int hp = 0; hp < 2; hp++) {
        if ((wc >> 1) == hp) {
            #pragma unroll
            for (int mi = 0; mi < 4; mi++) {
                int nl = wr * 64 + mi * 16 + g;
                #pragma unroll
                for (int ni = 0; ni < 4; ni++) {
                    int ol = (wc & 1) * 32 + ni * 8 + 2 * ti;
                    sm.tf[ol    ][nl    ] = acc[mi][ni][0];
                    sm.tf[ol + 1][nl    ] = acc[mi][ni][1];
                    sm.tf[ol    ][nl + 8] = acc[mi][ni][2];
                    sm.tf[ol + 1][nl + 8] = acc[mi][ni][3];
                }
            }
        }
        __syncthreads();
        int r = tid >> 2, qn = (tid & 3) * 32;
        int o = o0 + hp * 64 + r;
        float bo = bias[o];
        size_t bse = ((size_t)b * NC + o) * NHW + n0 + qn;
        #pragma unroll
        for (int j = 0; j < 32; j += 4) {
            float4 xv = *(const float4*)&x[bse + j];
            float4 tv = *(const float4*)&sm.tf[r][qn + j];
            float4 rv;
            rv.x = xv.x + tv.x + bo; rv.y = xv.y + tv.y + bo;
            rv.z = xv.z + tv.z + bo; rv.w = xv.w + tv.w + bo;
            *(float4*)&out[bse + j] = rv;
        }
        __syncthreads();
    }
}

// ---------------- launch ----------------
extern "C" void kernel_launch(void* const* d_in, const int* in_sizes, int n_in,
                              void* d_out, int out_size) {
    const float* x      = (const float*)d_in[0];
    const float* gns    = (const float*)d_in[1];
    const float* gnb    = (const float*)d_in[2];
    const float* wq     = (const float*)d_in[3];
    const float* bq     = (const float*)d_in[4];
    const float* wk     = (const float*)d_in[5];
    const float* bk     = (const float*)d_in[6];
    const float* wv     = (const float*)d_in[7];
    const float* bv     = (const float*)d_in[8];
    const float* wproj  = (const float*)d_in[9];
    const float* bproj  = (const float*)d_in[10];
    const float* dq     = (const float*)d_in[11];
    const float* zq     = (const float*)d_in[12];
    const float* dk     = (const float*)d_in[13];
    const float* zk     = (const float*)d_in[14];
    const float* dv     = (const float*)d_in[15];
    const float* zv     = (const float*)d_in[16];
    const float* dw     = (const float*)d_in[17];
    const float* zw     = (const float*)d_in[18];
    float* out = (float*)d_out;

    const int GSMEM = 4 * 128 * SPG * 2;   // 73728 B
    cudaFuncSetAttribute(gemm1_kernel, cudaFuncAttributeMaxDynamicSharedMemorySize, GSMEM);
    cudaFuncSetAttribute(gemm2_kernel, cudaFuncAttributeMaxDynamicSharedMemorySize, GSMEM);

    gn_kernel<<<NB * 32, 256>>>(x, gns, gnb);
    wsplit_kernel<<<256, 256>>>(wq, wk, wv, wproj);
    qkv_kernel<<<dim3(NHW / 128, NC / 128, NB * 3), 256>>>(
        bq, bk, bv, dq, zq, dk, zk, dv, zv);
    gemm1_kernel<<<dim3(NHW / 128, NHW / 128, NB), 256, GSMEM>>>(dq, dk);
    softmax_kernel<<<NB * NHW, 256>>>(dw, zw);
    gemm2_kernel<<<dim3(NHW / 128, NC / 128, NB), 256, GSMEM>>>(dv, dw);
    proj_kernel<<<dim3(NHW / 128, NC / 128, NB), 256>>>(x, bproj, out);
}

// round 13
// speedup vs baseline: 2.0530x; 2.0530x over previous
#include <cuda_runtime.h>
#include <cuda_bf16.h>
#include <cuda_fp16.h>
#include <cstdint>

#define NB 4
#define NC 256
#define NHW 4096
#define KT 32
#define SP 40    // padded smem row stride (bf16 elems) for conv kernels
#define KTG 64   // gemm1/gemm2 k-tile
#define SPG 72   // padded row stride for KTG tiles (144B, conflict-free)
#define CT2 64   // gemm2 c-tile (output channels per CTA)

// ---------------- scratch ----------------
__device__ __nv_bfloat16 g_hT_hi[NB*NHW*NC];
__device__ __nv_bfloat16 g_hT_lo[NB*NHW*NC];
__device__ __nv_bfloat16 g_w_hi[4*NC*NC];   // q,k,v,proj
__device__ __nv_bfloat16 g_w_lo[4*NC*NC];
__device__ __nv_bfloat16 g_q[NB*NHW*NC];    // quantized q codes [b][n][c]
__device__ __nv_bfloat16 g_k[NB*NHW*NC];    // quantized k codes [b][m][c]
__device__ __nv_bfloat16 g_v[NB*NC*NHW];    // quantized v codes [b][c][m]
__device__ __half        g_S[(size_t)NB*NHW*NHW];  // logits (f16)
__device__ __nv_bfloat16 g_a[(size_t)NB*NHW*NHW];  // quantized attn codes [b][n][m]
__device__ __nv_bfloat16 g_hoT_hi[NB*NHW*NC];
__device__ __nv_bfloat16 g_hoT_lo[NB*NHW*NC];

// ---------------- helpers ----------------
__device__ __forceinline__ void mma16816(float d[4], const uint32_t a[4], const uint32_t b[2]) {
    asm volatile(
        "mma.sync.aligned.m16n8k16.row.col.f32.bf16.bf16.f32 "
        "{%0,%1,%2,%3},{%4,%5,%6,%7},{%8,%9},{%0,%1,%2,%3};\n"
        : "+f"(d[0]), "+f"(d[1]), "+f"(d[2]), "+f"(d[3])
        : "r"(a[0]), "r"(a[1]), "r"(a[2]), "r"(a[3]), "r"(b[0]), "r"(b[1]));
}
__device__ __forceinline__ void ldsm4(uint32_t r[4], const void* p) {
    uint32_t a = (uint32_t)__cvta_generic_to_shared(p);
    asm volatile("ldmatrix.sync.aligned.m8n8.x4.shared.b16 {%0,%1,%2,%3},[%4];\n"
        : "=r"(r[0]), "=r"(r[1]), "=r"(r[2]), "=r"(r[3]) : "r"(a));
}
__device__ __forceinline__ void cp16(void* s, const void* g) {
    uint32_t sa = (uint32_t)__cvta_generic_to_shared(s);
    asm volatile("cp.async.cg.shared.global [%0],[%1],16;\n" :: "r"(sa), "l"(g));
}
#define CP_COMMIT() asm volatile("cp.async.commit_group;\n")
#define CP_WAIT0()  asm volatile("cp.async.wait_group 0;\n")
#define CP_WAIT1()  asm volatile("cp.async.wait_group 1;\n")

__device__ __forceinline__ float fq_code(float v, float dinv, float zp) {
    float q = rintf(v * dinv) + zp;
    q = fminf(fmaxf(q, 0.0f), 255.0f);
    return q - zp;
}

// ---------------- 1) GroupNorm -> hT hi/lo [b][n][c] ----------------
__global__ void __launch_bounds__(256) gn_kernel(const float* __restrict__ x,
                                                 const float* __restrict__ gam,
                                                 const float* __restrict__ bet) {
    int b = blockIdx.x >> 5, gr = blockIdx.x & 31;
    const float* xp = x + ((size_t)(b * NC) + gr * 8) * NHW;
    int tid = threadIdx.x;
    const int Nf4 = 8 * NHW / 4;
    const float4* x4 = (const float4*)xp;
    float s = 0.f, ss = 0.f;
    for (int i = tid; i < Nf4; i += 256) {
        float4 v = x4[i];
        s  += v.x + v.y + v.z + v.w;
        ss += v.x * v.x + v.y * v.y + v.z * v.z + v.w * v.w;
    }
    __shared__ float rs[8], rss[8], s_sc[8], s_sh[8];
    #pragma unroll
    for (int o = 16; o; o >>= 1) {
        s  += __shfl_down_sync(0xffffffffu, s, o);
        ss += __shfl_down_sync(0xffffffffu, ss, o);
    }
    if ((tid & 31) == 0) { rs[tid >> 5] = s; rss[tid >> 5] = ss; }
    __syncthreads();
    float ts = 0.f, tss = 0.f;
    #pragma unroll
    for (int k = 0; k < 8; k++) { ts += rs[k]; tss += rss[k]; }
    const float inv = 1.0f / (float)(8 * NHW);
    float mu = ts * inv;
    float var = tss * inv - mu * mu;
    float rstd = 1.0f / sqrtf(var + 1e-6f);
    if (tid < 8) {
        float gm = gam[gr * 8 + tid];
        s_sc[tid] = gm * rstd;
        s_sh[tid] = bet[gr * 8 + tid] - mu * gm * rstd;
    }
    __syncthreads();
    __nv_bfloat16* Hh = g_hT_hi + (size_t)b * NHW * NC + gr * 8;
    __nv_bfloat16* Hl = g_hT_lo + (size_t)b * NHW * NC + gr * 8;
    for (int n = tid; n < NHW; n += 256) {
        union { __nv_bfloat16 h[8]; uint4 u; } ph, pl;
        #pragma unroll
        for (int c = 0; c < 8; c++) {
            float v = xp[(size_t)c * NHW + n] * s_sc[c] + s_sh[c];
            __nv_bfloat16 hi = __float2bfloat16(v);
            ph.h[c] = hi;
            pl.h[c] = __float2bfloat16(v - __bfloat162float(hi));
        }
        *(uint4*)&Hh[(size_t)n * NC] = ph.u;
        *(uint4*)&Hl[(size_t)n * NC] = pl.u;
    }
}

// ---------------- 2) weight split ----------------
__global__ void __launch_bounds__(256) wsplit_kernel(const float* __restrict__ wq,
                                                     const float* __restrict__ wk,
                                                     const float* __restrict__ wv,
                                                     const float* __restrict__ wp) {
    int idx = blockIdx.x * 256 + threadIdx.x;
    const float* ws[4] = {wq, wk, wv, wp};
    #pragma unroll
    for (int m = 0; m < 4; m++) {
        float v = ws[m][idx];
        __nv_bfloat16 hi = __float2bfloat16(v);
        g_w_hi[m * NC * NC + idx] = hi;
        g_w_lo[m * NC * NC + idx] = __float2bfloat16(v - __bfloat162float(hi));
    }
}

// ---------------- 3) QKV: split-bf16 mma conv + quantize (ldmatrix) ----------------
__global__ void __launch_bounds__(256) qkv_kernel(
    const float* __restrict__ bq, const float* __restrict__ bk, const float* __restrict__ bv,
    const float* __restrict__ dqp, const float* __restrict__ zqp,
    const float* __restrict__ dkp, const float* __restrict__ zkp,
    const float* __restrict__ dvp, const float* __restrict__ zvp) {
    int z = blockIdx.z;
    int b = z / 3, which = z - b * 3;
    const __nv_bfloat16* Wh = g_w_hi + which * NC * NC;
    const __nv_bfloat16* Wl = g_w_lo + which * NC * NC;
    const float* bias;
    float d, zp;
    if (which == 0)      { bias = bq; d = dqp[0]; zp = zqp[0]; }
    else if (which == 1) { bias = bk; d = dkp[0]; zp = zkp[0]; }
    else                 { bias = bv; d = dvp[0]; zp = zvp[0]; }
    int n0 = blockIdx.x * 128, o0 = blockIdx.y * 128;
    const __nv_bfloat16* Ahg = g_hT_hi + (size_t)b * NHW * NC;
    const __nv_bfloat16* Alg = g_hT_lo + (size_t)b * NHW * NC;

    __shared__ union SmU {
        struct { __nv_bfloat16 Ah[128][SP], Al[128][SP], Bh[128][SP], Bl[128][SP]; } m;
        __nv_bfloat16 tb[128][136];
    } sm;

    int tid = threadIdx.x, warp = tid >> 5, lane = tid & 31;
    int g = lane >> 2, ti = lane & 3, wr = warp & 1, wc = warp >> 1;
    int la  = lane & 15;
    int kA  = ((lane >> 4) & 1) * 8;
    int lb  = (lane & 7) + ((lane >> 4) & 1) * 8;
    int kB  = ((lane >> 3) & 1) * 8;
    float acc[4][4][4] = {};

    for (int k0 = 0; k0 < NC; k0 += KT) {
        #pragma unroll
        for (int u = 0; u < 2; u++) {
            int c = tid + u * 256; int r = c >> 2, q = (c & 3) * 8;
            cp16(&sm.m.Ah[r][q], &Ahg[(size_t)(n0 + r) * NC + k0 + q]);
            cp16(&sm.m.Al[r][q], &Alg[(size_t)(n0 + r) * NC + k0 + q]);
            cp16(&sm.m.Bh[r][q], &Wh[(o0 + r) * NC + k0 + q]);
            cp16(&sm.m.Bl[r][q], &Wl[(o0 + r) * NC + k0 + q]);
        }
        CP_COMMIT(); CP_WAIT0();
        __syncthreads();
        #pragma unroll
        for (int kk = 0; kk < KT; kk += 16) {
            uint32_t ah[4][4], al[4][4], bh[2][4], bl[2][4];
            #pragma unroll
            for (int mi = 0; mi < 4; mi++) {
                int r = wr * 64 + mi * 16 + la;
                ldsm4(ah[mi], &sm.m.Ah[r][kk + kA]);
                ldsm4(al[mi], &sm.m.Al[r][kk + kA]);
            }
            #pragma unroll
            for (int nj = 0; nj < 2; nj++) {
                int c = wc * 32 + nj * 16 + lb;
                ldsm4(bh[nj], &sm.m.Bh[c][kk + kB]);
                ldsm4(bl[nj], &sm.m.Bl[c][kk + kB]);
            }
            #pragma unroll
            for (int mi = 0; mi < 4; mi++)
                #pragma unroll
                for (int ni = 0; ni < 4; ni++) {
                    mma16816(acc[mi][ni], ah[mi], &bh[ni >> 1][(ni & 1) * 2]);
                    mma16816(acc[mi][ni], ah[mi], &bl[ni >> 1][(ni & 1) * 2]);
                    mma16816(acc[mi][ni], al[mi], &bh[ni >> 1][(ni & 1) * 2]);
                }
        }
        __syncthreads();
    }

    float dinv = 1.0f / d;
    if (which < 2) {
        __nv_bfloat16* Out = (which == 0 ? g_q : g_k) + (size_t)b * NHW * NC;
        #pragma unroll
        for (int mi = 0; mi < 4; mi++) {
            int n = n0 + wr * 64 + mi * 16 + g;
            #pragma unroll
            for (int ni = 0; ni < 4; ni++) {
                int o = o0 + wc * 32 + ni * 8 + 2 * ti;
                float b0 = bias[o], b1 = bias[o + 1];
                union { __nv_bfloat16 h[2]; uint32_t u; } p0, p1;
                p0.h[0] = __float2bfloat16(fq_code(acc[mi][ni][0] + b0, dinv, zp));
                p0.h[1] = __float2bfloat16(fq_code(acc[mi][ni][1] + b1, dinv, zp));
                p1.h[0] = __float2bfloat16(fq_code(acc[mi][ni][2] + b0, dinv, zp));
                p1.h[1] = __float2bfloat16(fq_code(acc[mi][ni][3] + b1, dinv, zp));
                *(uint32_t*)&Out[(size_t)n * NC + o]       = p0.u;
                *(uint32_t*)&Out[(size_t)(n + 8) * NC + o] = p1.u;
            }
        }
    } else {
        #pragma unroll
        for (int mi = 0; mi < 4; mi++) {
            int nl = wr * 64 + mi * 16 + g;
            #pragma unroll
            for (int ni = 0; ni < 4; ni++) {
                int ol = wc * 32 + ni * 8 + 2 * ti;
                float b0 = bias[o0 + ol], b1 = bias[o0 + ol + 1];
                sm.tb[ol    ][nl    ] = __float2bfloat16(fq_code(acc[mi][ni][0] + b0, dinv, zp));
                sm.tb[ol + 1][nl    ] = __float2bfloat16(fq_code(acc[mi][ni][1] + b1, dinv, zp));
                sm.tb[ol    ][nl + 8] = __float2bfloat16(fq_code(acc[mi][ni][2] + b0, dinv, zp));
                sm.tb[ol + 1][nl + 8] = __float2bfloat16(fq_code(acc[mi][ni][3] + b1, dinv, zp));
            }
        }
        __syncthreads();
        int r = tid >> 1, half = (tid & 1) * 64;
        #pragma unroll
        for (int j = 0; j < 64; j += 8)
            *(uint4*)&g_v[((size_t)b * NC + o0 + r) * NHW + n0 + half + j] =
                *(uint4*)&sm.tb[r][half + j];
    }
}

// ---------------- 4) gemm1: S = q . k^T (bf16 mma, KTG=64, f16 out) ----------------
__global__ void __launch_bounds__(256) gemm1_kernel(const float* __restrict__ dqp,
                                                    const float* __restrict__ dkp) {
    extern __shared__ __nv_bfloat16 ds[];
    __nv_bfloat16 (*As)[128][SPG] = (__nv_bfloat16 (*)[128][SPG])ds;
    __nv_bfloat16 (*Bs)[128][SPG] = (__nv_bfloat16 (*)[128][SPG])(ds + 2 * 128 * SPG);

    int b = blockIdx.z, m0 = blockIdx.x * 128, n0 = blockIdx.y * 128;
    const __nv_bfloat16* A  = g_q + (size_t)b * NHW * NC;
    const __nv_bfloat16* Bm = g_k + (size_t)b * NHW * NC;
    int tid = threadIdx.x, warp = tid >> 5, lane = tid & 31;
    int g = lane >> 2, ti = lane & 3, wr = warp & 1, wc = warp >> 1;
    int la  = lane & 15;
    int kA  = ((lane >> 4) & 1) * 8;
    int lb  = (lane & 7) + ((lane >> 4) & 1) * 8;
    int kB  = ((lane >> 3) & 1) * 8;
    float acc[4][4][4] = {};
    #pragma unroll
    for (int u = 0; u < 4; u++) {
        int c = tid + u * 256; int r = c >> 3, q = (c & 7) * 8;
        cp16(&As[0][r][q], &A [(size_t)(n0 + r) * NC + q]);
        cp16(&Bs[0][r][q], &Bm[(size_t)(m0 + r) * NC + q]);
    }
    CP_COMMIT();
    const int T = NC / KTG;   // 4
    for (int t = 0; t < T; t++) {
        if (t + 1 < T) {
            int k0 = (t + 1) * KTG, bi = (t + 1) & 1;
            #pragma unroll
            for (int u = 0; u < 4; u++) {
                int c = tid + u * 256; int r = c >> 3, q = (c & 7) * 8;
                cp16(&As[bi][r][q], &A [(size_t)(n0 + r) * NC + k0 + q]);
                cp16(&Bs[bi][r][q], &Bm[(size_t)(m0 + r) * NC + k0 + q]);
            }
            CP_COMMIT(); CP_WAIT1();
        } else CP_WAIT0();
        __syncthreads();
        int bi = t & 1;
        #pragma unroll
        for (int kk = 0; kk < KTG; kk += 16) {
            uint32_t af[4][4], bf[2][4];
            #pragma unroll
            for (int mi = 0; mi < 4; mi++)
                ldsm4(af[mi], &As[bi][wr * 64 + mi * 16 + la][kk + kA]);
            #pragma unroll
            for (int nj = 0; nj < 2; nj++)
                ldsm4(bf[nj], &Bs[bi][wc * 32 + nj * 16 + lb][kk + kB]);
            #pragma unroll
            for (int mi = 0; mi < 4; mi++)
                #pragma unroll
                for (int ni = 0; ni < 4; ni++)
                    mma16816(acc[mi][ni], af[mi], &bf[ni >> 1][(ni & 1) * 2]);
        }
        __syncthreads();
    }
    float sc = dqp[0] * dkp[0] * 0.0625f;
    __half* Sp = g_S + (size_t)b * NHW * NHW;
    #pragma unroll
    for (int mi = 0; mi < 4; mi++) {
        int n = n0 + wr * 64 + mi * 16 + g;
        #pragma unroll
        for (int ni = 0; ni < 4; ni++) {
            int m = m0 + wc * 32 + ni * 8 + 2 * ti;
            *(__half2*)&Sp[(size_t)n * NHW + m] =
                __floats2half2_rn(acc[mi][ni][0] * sc, acc[mi][ni][1] * sc);
            *(__half2*)&Sp[(size_t)(n + 8) * NHW + m] =
                __floats2half2_rn(acc[mi][ni][2] * sc, acc[mi][ni][3] * sc);
        }
    }
}

// ---------------- 5) softmax + 8-bit quantize (f16 in, bf16 codes out) ----------------
__global__ void __launch_bounds__(256) softmax_kernel(const float* __restrict__ dwp,
                                                      const float* __restrict__ zwp) {
    size_t row = blockIdx.x;
    const __half* s = g_S + row * NHW;
    __nv_bfloat16* a = g_a + row * NHW;
    int tid = threadIdx.x;
    float v[16];
    #pragma unroll
    for (int j = 0; j < 2; j++) {
        uint4 t = *(const uint4*)&s[(j * 256 + tid) * 8];
        const __half2* hp = (const __half2*)&t;
        #pragma unroll
        for (int l = 0; l < 4; l++) {
            float2 f = __half22float2(hp[l]);
            v[j * 8 + 2 * l]     = f.x;
            v[j * 8 + 2 * l + 1] = f.y;
        }
    }
    float mx = -3.4e38f;
    #pragma unroll
    for (int i = 0; i < 16; i++) mx = fmaxf(mx, v[i]);
    __shared__ float red[8];
    #pragma unroll
    for (int o = 16; o; o >>= 1) mx = fmaxf(mx, __shfl_xor_sync(0xffffffffu, mx, o));
    if ((tid & 31) == 0) red[tid >> 5] = mx;
    __syncthreads();
    mx = red[0];
    #pragma unroll
    for (int k = 1; k < 8; k++) mx = fmaxf(mx, red[k]);
    __syncthreads();
    float sum = 0.f;
    #pragma unroll
    for (int i = 0; i < 16; i++) { v[i] = __expf(v[i] - mx); sum += v[i]; }
    #pragma unroll
    for (int o = 16; o; o >>= 1) sum += __shfl_xor_sync(0xffffffffu, sum, o);
    if ((tid & 31) == 0) red[tid >> 5] = sum;
    __syncthreads();
    sum = 0.f;
    #pragma unroll
    for (int k = 0; k < 8; k++) sum += red[k];
    float rinv = 1.0f / sum;
    float dinv = 1.0f / dwp[0], zw = zwp[0];
    #pragma unroll
    for (int j = 0; j < 2; j++) {
        union { __nv_bfloat16 h[8]; uint4 u; } pk;
        #pragma unroll
        for (int l = 0; l < 8; l++)
            pk.h[l] = __float2bfloat16(fq_code(v[j * 8 + l] * rinv, dinv, zw));
        *(uint4*)&a[(j * 256 + tid) * 8] = pk.u;
    }
}

// ---------------- 6) gemm2: hoT = a . v^T (128x64 tiles, KTG=64) ----------------
__global__ void __launch_bounds__(256) gemm2_kernel(const float* __restrict__ dvp,
                                                    const float* __restrict__ dwp) {
    extern __shared__ __nv_bfloat16 ds[];
    __nv_bfloat16 (*As)[128][SPG] = (__nv_bfloat16 (*)[128][SPG])ds;
    __nv_bfloat16 (*Bs)[CT2][SPG] = (__nv_bfloat16 (*)[CT2][SPG])(ds + 2 * 128 * SPG);

    int b = blockIdx.z, n0 = blockIdx.x * 128, c0 = blockIdx.y * CT2;
    const __nv_bfloat16* A  = g_a + (size_t)b * NHW * NHW;   // [n][m]
    const __nv_bfloat16* Bm = g_v + (size_t)b * NC * NHW;    // [c][m]
    int tid = threadIdx.x, warp = tid >> 5, lane = tid & 31;
    int g = lane >> 2, ti = lane & 3, wr = warp & 1, wc = warp >> 1;  // wc: 0..3 -> 16-col slice
    int la  = lane & 15;
    int kA  = ((lane >> 4) & 1) * 8;
    int lb  = (lane & 7) + ((lane >> 4) & 1) * 8;
    int kB  = ((lane >> 3) & 1) * 8;
    float acc[4][2][4] = {};
    #pragma unroll
    for (int u = 0; u < 4; u++) {
        int c = tid + u * 256; int r = c >> 3, q = (c & 7) * 8;
        cp16(&As[0][r][q], &A[(size_t)(n0 + r) * NHW + q]);
    }
    #pragma unroll
    for (int u = 0; u < 2; u++) {
        int c = tid + u * 256; int r = c >> 3, q = (c & 7) * 8;
        cp16(&Bs[0][r][q], &Bm[(size_t)(c0 + r) * NHW + q]);
    }
    CP_COMMIT();
    const int T = NHW / KTG;  // 64
    for (int t = 0; t < T; t++) {
        if (t + 1 < T) {
            int k0 = (t + 1) * KTG, bi = (t + 1) & 1;
            #pragma unroll
            for (int u = 0; u < 4; u++) {
                int c = tid + u * 256; int r = c >> 3, q = (c & 7) * 8;
                cp16(&As[bi][r][q], &A[(size_t)(n0 + r) * NHW + k0 + q]);
            }
            #pragma unroll
            for (int u = 0; u < 2; u++) {
                int c = tid + u * 256; int r = c >> 3, q = (c & 7) * 8;
                cp16(&Bs[bi][r][q], &Bm[(size_t)(c0 + r) * NHW + k0 + q]);
            }
            CP_COMMIT(); CP_WAIT1();
        } else CP_WAIT0();
        __syncthreads();
        int bi = t & 1;
        #pragma unroll
        for (int kk = 0; kk < KTG; kk += 16) {
            uint32_t af[4][4], bf[4];
            #pragma unroll
            for (int mi = 0; mi < 4; mi++)
                ldsm4(af[mi], &As[bi][wr * 64 + mi * 16 + la][kk + kA]);
            ldsm4(bf, &Bs[bi][wc * 16 + lb][kk + kB]);
            #pragma unroll
            for (int mi = 0; mi < 4; mi++)
                #pragma unroll
                for (int ni = 0; ni < 2; ni++)
                    mma16816(acc[mi][ni], af[mi], &bf[ni * 2]);
        }
        __syncthreads();
    }
    float sc = dvp[0] * dwp[0];
    __nv_bfloat16* Oh = g_hoT_hi + (size_t)b * NHW * NC;
    __nv_bfloat16* Ol = g_hoT_lo + (size_t)b * NHW * NC;
    #pragma unroll
    for (int mi = 0; mi < 4; mi++) {
        int n = n0 + wr * 64 + mi * 16 + g;
        #pragma unroll
        for (int ni = 0; ni < 2; ni++) {
            int c = c0 + wc * 16 + ni * 8 + 2 * ti;
            #pragma unroll
            for (int half = 0; half < 2; half++) {
                float v0 = acc[mi][ni][2 * half] * sc;
                float v1 = acc[mi][ni][2 * half + 1] * sc;
                __nv_bfloat16 h0 = __float2bfloat16(v0);
                __nv_bfloat16 h1 = __float2bfloat16(v1);
                union { __nv_bfloat16 h[2]; uint32_t u; } ph, pl;
                ph.h[0] = h0; ph.h[1] = h1;
                pl.h[0] = __float2bfloat16(v0 - __bfloat162float(h0));
                pl.h[1] = __float2bfloat16(v1 - __bfloat162float(h1));
                size_t off = (size_t)(n + 8 * half) * NC + c;
                *(uint32_t*)&Oh[off] = ph.u;
                *(uint32_t*)&Ol[off] = pl.u;
            }
        }
    }
}

// ---------------- 7) proj: split-bf16 mma + bias + residual (ldmatrix) ----------------
__global__ void __launch_bounds__(256) proj_kernel(const float* __restrict__ x,
                                                   const float* __restrict__ bias,
                                                   float* __restrict__ out) {
    int b = blockIdx.z;
    int n0 = blockIdx.x * 128, o0 = blockIdx.y * 128;
    const __nv_bfloat16* Wh = g_w_hi + 3 * NC * NC;
    const __nv_bfloat16* Wl = g_w_lo + 3 * NC * NC;
    const __nv_bfloat16* Ahg = g_hoT_hi + (size_t)b * NHW * NC;
    const __nv_bfloat16* Alg = g_hoT_lo + (size_t)b * NHW * NC;

    __shared__ union SmU {
        struct { __nv_bfloat16 Ah[128][SP], Al[128][SP], Bh[128][SP], Bl[128][SP]; } m;
        float tf[64][132];
    } sm;

    int tid = threadIdx.x, warp = tid >> 5, lane = tid & 31;
    int g = lane >> 2, ti = lane & 3, wr = warp & 1, wc = warp >> 1;
    int la  = lane & 15;
    int kA  = ((lane >> 4) & 1) * 8;
    int lb  = (lane & 7) + ((lane >> 4) & 1) * 8;
    int kB  = ((lane >> 3) & 1) * 8;
    float acc[4][4][4] = {};

    for (int k0 = 0; k0 < NC; k0 += KT) {
        #pragma unroll
        for (int u = 0; u < 2; u++) {
            int c = tid + u * 256; int r = c >> 2, q = (c & 3) * 8;
            cp16(&sm.m.Ah[r][q], &Ahg[(size_t)(n0 + r) * NC + k0 + q]);
            cp16(&sm.m.Al[r][q], &Alg[(size_t)(n0 + r) * NC + k0 + q]);
            cp16(&sm.m.Bh[r][q], &Wh[(o0 + r) * NC + k0 + q]);
            cp16(&sm.m.Bl[r][q], &Wl[(o0 + r) * NC + k0 + q]);
        }
        CP_COMMIT(); CP_WAIT0();
        __syncthreads();
        #pragma unroll
        for (int kk = 0; kk < KT; kk += 16) {
            uint32_t ah[4][4], al[4][4], bh[2][4], bl[2][4];
            #pragma unroll
            for (int mi = 0; mi < 4; mi++) {
                int r = wr * 64 + mi * 16 + la;
                ldsm4(ah[mi], &sm.m.Ah[r][kk + kA]);
                ldsm4(al[mi], &sm.m.Al[r][kk + kA]);
            }
            #pragma unroll
            for (int nj = 0; nj < 2; nj++) {
                int c = wc * 32 + nj * 16 + lb;
                ldsm4(bh[nj], &sm.m.Bh[c][kk + kB]);
                ldsm4(bl[nj], &sm.m.Bl[c][kk + kB]);
            }
            #pragma unroll
            for (int mi = 0; mi < 4; mi++)
                #pragma unroll
                for (int ni = 0; ni < 4; ni++) {
                    mma16816(acc[mi][ni], ah[mi], &bh[ni >> 1][(ni & 1) * 2]);
                    mma16816(acc[mi][ni], ah[mi], &bl[ni >> 1][(ni & 1) * 2]);
                    mma16816(acc[mi][ni], al[mi], &bh[ni >> 1][(ni & 1) * 2]);
                }
        }
        __syncthreads();
    }

    #pragma unroll
    for (int hp = 0; hp < 2; hp++) {
        if ((wc >> 1) == hp) {
            #pragma unroll
            for (int mi = 0; mi < 4; mi++) {
                int nl = wr * 64 + mi * 16 + g;
                #pragma unroll
                for (int ni = 0; ni < 4; ni++) {
                    int ol = (wc & 1) * 32 + ni * 8 + 2 * ti;
                    sm.tf[ol    ][nl    ] = acc[mi][ni][0];
                    sm.tf[ol + 1][nl    ] = acc[mi][ni][1];
                    sm.tf[ol    ][nl + 8] = acc[mi][ni][2];
                    sm.tf[ol + 1][nl + 8] = acc[mi][ni][3];
                }
            }
        }
        __syncthreads();
        int r = tid >> 2, qn = (tid & 3) * 32;
        int o = o0 + hp * 64 + r;
        float bo = bias[o];
        size_t bse = ((size_t)b * NC + o) * NHW + n0 + qn;
        #pragma unroll
        for (int j = 0; j < 32; j += 4) {
            float4 xv = *(const float4*)&x[bse + j];
            float4 tv = *(const float4*)&sm.tf[r][qn + j];
            float4 rv;
            rv.x = xv.x + tv.x + bo; rv.y = xv.y + tv.y + bo;
            rv.z = xv.z + tv.z + bo; rv.w = xv.w + tv.w + bo;
            *(float4*)&out[bse + j] = rv;
        }
        __syncthreads();
    }
}

// ---------------- launch ----------------
extern "C" void kernel_launch(void* const* d_in, const int* in_sizes, int n_in,
                              void* d_out, int out_size) {
    const float* x      = (const float*)d_in[0];
    const float* gns    = (const float*)d_in[1];
    const float* gnb    = (const float*)d_in[2];
    const float* wq     = (const float*)d_in[3];
    const float* bq     = (const float*)d_in[4];
    const float* wk     = (const float*)d_in[5];
    const float* bk     = (const float*)d_in[6];
    const float* wv     = (const float*)d_in[7];
    const float* bv     = (const float*)d_in[8];
    const float* wproj  = (const float*)d_in[9];
    const float* bproj  = (const float*)d_in[10];
    const float* dq     = (const float*)d_in[11];
    const float* zq     = (const float*)d_in[12];
    const float* dk     = (const float*)d_in[13];
    const float* zk     = (const float*)d_in[14];
    const float* dv     = (const float*)d_in[15];
    const float* zv     = (const float*)d_in[16];
    const float* dw     = (const float*)d_in[17];
    const float* zw     = (const float*)d_in[18];
    float* out = (float*)d_out;

    const int GSMEM1 = 4 * 128 * SPG * 2;            // 73728 B
    const int GSMEM2 = 2 * (128 + CT2) * SPG * 2;    // 55296 B
    cudaFuncSetAttribute(gemm1_kernel, cudaFuncAttributeMaxDynamicSharedMemorySize, GSMEM1);
    cudaFuncSetAttribute(gemm2_kernel, cudaFuncAttributeMaxDynamicSharedMemorySize, GSMEM2);

    gn_kernel<<<NB * 32, 256>>>(x, gns, gnb);
    wsplit_kernel<<<256, 256>>>(wq, wk, wv, wproj);
    qkv_kernel<<<dim3(NHW / 128, NC / 128, NB * 3), 256>>>(
        bq, bk, bv, dq, zq, dk, zk, dv, zv);
    gemm1_kernel<<<dim3(NHW / 128, NHW / 128, NB), 256, GSMEM1>>>(dq, dk);
    softmax_kernel<<<NB * NHW, 256>>>(dw, zw);
    gemm2_kernel<<<dim3(NHW / 128, NC / CT2, NB), 256, GSMEM2>>>(dv, dw);
    proj_kernel<<<dim3(NHW / 128, NC / 128, NB), 256>>>(x, bproj, out);
}

// round 14
// speedup vs baseline: 2.1589x; 1.0516x over previous
#include <cuda_runtime.h>
#include <cuda_bf16.h>
#include <cuda_fp16.h>
#include <cstdint>

#define NB 4
#define NC 256
#define NHW 4096
#define KT 32
#define SP 40    // padded smem row stride (bf16 elems) for conv kernels
#define KTG 64   // gemm1/gemm2 k-tile
#define SPG 72   // padded row stride for KTG tiles (144B, conflict-free)

// ---------------- scratch ----------------
__device__ __nv_bfloat16 g_hT_hi[NB*NHW*NC];
__device__ __nv_bfloat16 g_hT_lo[NB*NHW*NC];
__device__ __nv_bfloat16 g_w_hi[4*NC*NC];   // q,k,v,proj
__device__ __nv_bfloat16 g_w_lo[4*NC*NC];
__device__ __nv_bfloat16 g_q[NB*NHW*NC];    // quantized q codes [b][n][c]
__device__ __nv_bfloat16 g_k[NB*NHW*NC];    // quantized k codes [b][m][c]
__device__ __nv_bfloat16 g_v[NB*NC*NHW];    // quantized v codes [b][c][m]
__device__ __half        g_S[(size_t)NB*NHW*NHW];  // logits (f16)
__device__ __nv_bfloat16 g_a[(size_t)NB*NHW*NHW];  // quantized attn codes [b][n][m]
__device__ __nv_bfloat16 g_hoT_hi[NB*NHW*NC];
__device__ __nv_bfloat16 g_hoT_lo[NB*NHW*NC];

// ---------------- helpers ----------------
__device__ __forceinline__ void mma16816(float d[4], const uint32_t a[4], const uint32_t b[2]) {
    asm volatile(
        "mma.sync.aligned.m16n8k16.row.col.f32.bf16.bf16.f32 "
        "{%0,%1,%2,%3},{%4,%5,%6,%7},{%8,%9},{%0,%1,%2,%3};\n"
        : "+f"(d[0]), "+f"(d[1]), "+f"(d[2]), "+f"(d[3])
        : "r"(a[0]), "r"(a[1]), "r"(a[2]), "r"(a[3]), "r"(b[0]), "r"(b[1]));
}
__device__ __forceinline__ void ldsm4(uint32_t r[4], const void* p) {
    uint32_t a = (uint32_t)__cvta_generic_to_shared(p);
    asm volatile("ldmatrix.sync.aligned.m8n8.x4.shared.b16 {%0,%1,%2,%3},[%4];\n"
        : "=r"(r[0]), "=r"(r[1]), "=r"(r[2]), "=r"(r[3]) : "r"(a));
}
__device__ __forceinline__ void cp16(void* s, const void* g) {
    uint32_t sa = (uint32_t)__cvta_generic_to_shared(s);
    asm volatile("cp.async.cg.shared.global [%0],[%1],16;\n" :: "r"(sa), "l"(g));
}
#define CP_COMMIT() asm volatile("cp.async.commit_group;\n")
#define CP_WAIT0()  asm volatile("cp.async.wait_group 0;\n")
#define CP_WAIT1()  asm volatile("cp.async.wait_group 1;\n")

__device__ __forceinline__ float fq_code(float v, float dinv, float zp) {
    float q = rintf(v * dinv) + zp;
    q = fminf(fmaxf(q, 0.0f), 255.0f);
    return q - zp;
}

// ---------------- 1) GroupNorm -> hT hi/lo [b][n][c] ----------------
__global__ void __launch_bounds__(256) gn_kernel(const float* __restrict__ x,
                                                 const float* __restrict__ gam,
                                                 const float* __restrict__ bet) {
    int b = blockIdx.x >> 5, gr = blockIdx.x & 31;
    const float* xp = x + ((size_t)(b * NC) + gr * 8) * NHW;
    int tid = threadIdx.x;
    const int Nf4 = 8 * NHW / 4;
    const float4* x4 = (const float4*)xp;
    float s = 0.f, ss = 0.f;
    for (int i = tid; i < Nf4; i += 256) {
        float4 v = x4[i];
        s  += v.x + v.y + v.z + v.w;
        ss += v.x * v.x + v.y * v.y + v.z * v.z + v.w * v.w;
    }
    __shared__ float rs[8], rss[8], s_sc[8], s_sh[8];
    #pragma unroll
    for (int o = 16; o; o >>= 1) {
        s  += __shfl_down_sync(0xffffffffu, s, o);
        ss += __shfl_down_sync(0xffffffffu, ss, o);
    }
    if ((tid & 31) == 0) { rs[tid >> 5] = s; rss[tid >> 5] = ss; }
    __syncthreads();
    float ts = 0.f, tss = 0.f;
    #pragma unroll
    for (int k = 0; k < 8; k++) { ts += rs[k]; tss += rss[k]; }
    const float inv = 1.0f / (float)(8 * NHW);
    float mu = ts * inv;
    float var = tss * inv - mu * mu;
    float rstd = 1.0f / sqrtf(var + 1e-6f);
    if (tid < 8) {
        float gm = gam[gr * 8 + tid];
        s_sc[tid] = gm * rstd;
        s_sh[tid] = bet[gr * 8 + tid] - mu * gm * rstd;
    }
    __syncthreads();
    __nv_bfloat16* Hh = g_hT_hi + (size_t)b * NHW * NC + gr * 8;
    __nv_bfloat16* Hl = g_hT_lo + (size_t)b * NHW * NC + gr * 8;
    for (int n = tid; n < NHW; n += 256) {
        union { __nv_bfloat16 h[8]; uint4 u; } ph, pl;
        #pragma unroll
        for (int c = 0; c < 8; c++) {
            float v = xp[(size_t)c * NHW + n] * s_sc[c] + s_sh[c];
            __nv_bfloat16 hi = __float2bfloat16(v);
            ph.h[c] = hi;
            pl.h[c] = __float2bfloat16(v - __bfloat162float(hi));
        }
        *(uint4*)&Hh[(size_t)n * NC] = ph.u;
        *(uint4*)&Hl[(size_t)n * NC] = pl.u;
    }
}

// ---------------- 2) weight split ----------------
__global__ void __launch_bounds__(256) wsplit_kernel(const float* __restrict__ wq,
                                                     const float* __restrict__ wk,
                                                     const float* __restrict__ wv,
                                                     const float* __restrict__ wp) {
    int idx = blockIdx.x * 256 + threadIdx.x;
    const float* ws[4] = {wq, wk, wv, wp};
    #pragma unroll
    for (int m = 0; m < 4; m++) {
        float v = ws[m][idx];
        __nv_bfloat16 hi = __float2bfloat16(v);
        g_w_hi[m * NC * NC + idx] = hi;
        g_w_lo[m * NC * NC + idx] = __float2bfloat16(v - __bfloat162float(hi));
    }
}

// ---------------- 3) QKV: split-bf16 mma conv + quantize (double-buffered) ----------------
// dyn smem: tiles[2][4][128][SP] bf16 = 81920 B; u8/bf16 transpose buffer aliases base
__global__ void __launch_bounds__(256) qkv_kernel(
    const float* __restrict__ bq, const float* __restrict__ bk, const float* __restrict__ bv,
    const float* __restrict__ dqp, const float* __restrict__ zqp,
    const float* __restrict__ dkp, const float* __restrict__ zkp,
    const float* __restrict__ dvp, const float* __restrict__ zvp) {
    extern __shared__ char qsm[];
    __nv_bfloat16 (*tiles)[4][128][SP] = (__nv_bfloat16 (*)[4][128][SP])qsm;   // [stage][arr]
    __nv_bfloat16 (*tb)[136] = (__nv_bfloat16 (*)[136])qsm;                    // epilogue alias

    int z = blockIdx.z;
    int b = z / 3, which = z - b * 3;
    const __nv_bfloat16* Wh = g_w_hi + which * NC * NC;
    const __nv_bfloat16* Wl = g_w_lo + which * NC * NC;
    const float* bias;
    float d, zp;
    if (which == 0)      { bias = bq; d = dqp[0]; zp = zqp[0]; }
    else if (which == 1) { bias = bk; d = dkp[0]; zp = zkp[0]; }
    else                 { bias = bv; d = dvp[0]; zp = zvp[0]; }
    int n0 = blockIdx.x * 128, o0 = blockIdx.y * 128;
    const __nv_bfloat16* Ahg = g_hT_hi + (size_t)b * NHW * NC;
    const __nv_bfloat16* Alg = g_hT_lo + (size_t)b * NHW * NC;

    int tid = threadIdx.x, warp = tid >> 5, lane = tid & 31;
    int g = lane >> 2, ti = lane & 3, wr = warp & 1, wc = warp >> 1;
    int la  = lane & 15;
    int kA  = ((lane >> 4) & 1) * 8;
    int lb  = (lane & 7) + ((lane >> 4) & 1) * 8;
    int kB  = ((lane >> 3) & 1) * 8;
    float acc[4][4][4] = {};

    // stage loader: each of 512 jobs covers one 8-col quarter of one row per array
    #define QKV_LOAD(st, k0)                                                        \
        do {                                                                        \
            _Pragma("unroll")                                                       \
            for (int u = 0; u < 2; u++) {                                           \
                int c = tid + u * 256; int r = c >> 2, q = (c & 3) * 8;             \
                cp16(&tiles[st][0][r][q], &Ahg[(size_t)(n0 + r) * NC + (k0) + q]);  \
                cp16(&tiles[st][1][r][q], &Alg[(size_t)(n0 + r) * NC + (k0) + q]);  \
                cp16(&tiles[st][2][r][q], &Wh[(o0 + r) * NC + (k0) + q]);           \
                cp16(&tiles[st][3][r][q], &Wl[(o0 + r) * NC + (k0) + q]);           \
            }                                                                       \
        } while (0)

    QKV_LOAD(0, 0);
    CP_COMMIT();
    const int T = NC / KT;   // 8
    for (int t = 0; t < T; t++) {
        if (t + 1 < T) {
            QKV_LOAD((t + 1) & 1, (t + 1) * KT);
            CP_COMMIT(); CP_WAIT1();
        } else CP_WAIT0();
        __syncthreads();
        int bi = t & 1;
        #pragma unroll
        for (int kk = 0; kk < KT; kk += 16) {
            uint32_t ah[4][4], al[4][4], bh[2][4], bl[2][4];
            #pragma unroll
            for (int mi = 0; mi < 4; mi++) {
                int r = wr * 64 + mi * 16 + la;
                ldsm4(ah[mi], &tiles[bi][0][r][kk + kA]);
                ldsm4(al[mi], &tiles[bi][1][r][kk + kA]);
            }
            #pragma unroll
            for (int nj = 0; nj < 2; nj++) {
                int c = wc * 32 + nj * 16 + lb;
                ldsm4(bh[nj], &tiles[bi][2][c][kk + kB]);
                ldsm4(bl[nj], &tiles[bi][3][c][kk + kB]);
            }
            #pragma unroll
            for (int mi = 0; mi < 4; mi++)
                #pragma unroll
                for (int ni = 0; ni < 4; ni++) {
                    mma16816(acc[mi][ni], ah[mi], &bh[ni >> 1][(ni & 1) * 2]);
                    mma16816(acc[mi][ni], ah[mi], &bl[ni >> 1][(ni & 1) * 2]);
                    mma16816(acc[mi][ni], al[mi], &bh[ni >> 1][(ni & 1) * 2]);
                }
        }
        __syncthreads();
    }
    #undef QKV_LOAD

    float dinv = 1.0f / d;
    if (which < 2) {
        __nv_bfloat16* Out = (which == 0 ? g_q : g_k) + (size_t)b * NHW * NC;
        #pragma unroll
        for (int mi = 0; mi < 4; mi++) {
            int n = n0 + wr * 64 + mi * 16 + g;
            #pragma unroll
            for (int ni = 0; ni < 4; ni++) {
                int o = o0 + wc * 32 + ni * 8 + 2 * ti;
                float b0 = bias[o], b1 = bias[o + 1];
                union { __nv_bfloat16 h[2]; uint32_t u; } p0, p1;
                p0.h[0] = __float2bfloat16(fq_code(acc[mi][ni][0] + b0, dinv, zp));
                p0.h[1] = __float2bfloat16(fq_code(acc[mi][ni][1] + b1, dinv, zp));
                p1.h[0] = __float2bfloat16(fq_code(acc[mi][ni][2] + b0, dinv, zp));
                p1.h[1] = __float2bfloat16(fq_code(acc[mi][ni][3] + b1, dinv, zp));
                *(uint32_t*)&Out[(size_t)n * NC + o]       = p0.u;
                *(uint32_t*)&Out[(size_t)(n + 8) * NC + o] = p1.u;
            }
        }
    } else {
        #pragma unroll
        for (int mi = 0; mi < 4; mi++) {
            int nl = wr * 64 + mi * 16 + g;
            #pragma unroll
            for (int ni = 0; ni < 4; ni++) {
                int ol = wc * 32 + ni * 8 + 2 * ti;
                float b0 = bias[o0 + ol], b1 = bias[o0 + ol + 1];
                tb[ol    ][nl    ] = __float2bfloat16(fq_code(acc[mi][ni][0] + b0, dinv, zp));
                tb[ol + 1][nl    ] = __float2bfloat16(fq_code(acc[mi][ni][1] + b1, dinv, zp));
                tb[ol    ][nl + 8] = __float2bfloat16(fq_code(acc[mi][ni][2] + b0, dinv, zp));
                tb[ol + 1][nl + 8] = __float2bfloat16(fq_code(acc[mi][ni][3] + b1, dinv, zp));
            }
        }
        __syncthreads();
        int r = tid >> 1, half = (tid & 1) * 64;
        #pragma unroll
        for (int j = 0; j < 64; j += 8)
            *(uint4*)&g_v[((size_t)b * NC + o0 + r) * NHW + n0 + half + j] =
                *(uint4*)&tb[r][half + j];
    }
}

// ---------------- 4) gemm1: S = q . k^T (bf16 mma, KTG=64, f16 out) ----------------
__global__ void __launch_bounds__(256) gemm1_kernel(const float* __restrict__ dqp,
                                                    const float* __restrict__ dkp) {
    extern __shared__ __nv_bfloat16 ds[];
    __nv_bfloat16 (*As)[128][SPG] = (__nv_bfloat16 (*)[128][SPG])ds;
    __nv_bfloat16 (*Bs)[128][SPG] = (__nv_bfloat16 (*)[128][SPG])(ds + 2 * 128 * SPG);

    int b = blockIdx.z, m0 = blockIdx.x * 128, n0 = blockIdx.y * 128;
    const __nv_bfloat16* A  = g_q + (size_t)b * NHW * NC;
    const __nv_bfloat16* Bm = g_k + (size_t)b * NHW * NC;
    int tid = threadIdx.x, warp = tid >> 5, lane = tid & 31;
    int g = lane >> 2, ti = lane & 3, wr = warp & 1, wc = warp >> 1;
    int la  = lane & 15;
    int kA  = ((lane >> 4) & 1) * 8;
    int lb  = (lane & 7) + ((lane >> 4) & 1) * 8;
    int kB  = ((lane >> 3) & 1) * 8;
    float acc[4][4][4] = {};
    #pragma unroll
    for (int u = 0; u < 4; u++) {
        int c = tid + u * 256; int r = c >> 3, q = (c & 7) * 8;
        cp16(&As[0][r][q], &A [(size_t)(n0 + r) * NC + q]);
        cp16(&Bs[0][r][q], &Bm[(size_t)(m0 + r) * NC + q]);
    }
    CP_COMMIT();
    const int T = NC / KTG;   // 4
    for (int t = 0; t < T; t++) {
        if (t + 1 < T) {
            int k0 = (t + 1) * KTG, bi = (t + 1) & 1;
            #pragma unroll
            for (int u = 0; u < 4; u++) {
                int c = tid + u * 256; int r = c >> 3, q = (c & 7) * 8;
                cp16(&As[bi][r][q], &A [(size_t)(n0 + r) * NC + k0 + q]);
                cp16(&Bs[bi][r][q], &Bm[(size_t)(m0 + r) * NC + k0 + q]);
            }
            CP_COMMIT(); CP_WAIT1();
        } else CP_WAIT0();
        __syncthreads();
        int bi = t & 1;
        #pragma unroll
        for (int kk = 0; kk < KTG; kk += 16) {
            uint32_t af[4][4], bf[2][4];
            #pragma unroll
            for (int mi = 0; mi < 4; mi++)
                ldsm4(af[mi], &As[bi][wr * 64 + mi * 16 + la][kk + kA]);
            #pragma unroll
            for (int nj = 0; nj < 2; nj++)
                ldsm4(bf[nj], &Bs[bi][wc * 32 + nj * 16 + lb][kk + kB]);
            #pragma unroll
            for (int mi = 0; mi < 4; mi++)
                #pragma unroll
                for (int ni = 0; ni < 4; ni++)
                    mma16816(acc[mi][ni], af[mi], &bf[ni >> 1][(ni & 1) * 2]);
        }
        __syncthreads();
    }
    float sc = dqp[0] * dkp[0] * 0.0625f;
    __half* Sp = g_S + (size_t)b * NHW * NHW;
    #pragma unroll
    for (int mi = 0; mi < 4; mi++) {
        int n = n0 + wr * 64 + mi * 16 + g;
        #pragma unroll
        for (int ni = 0; ni < 4; ni++) {
            int m = m0 + wc * 32 + ni * 8 + 2 * ti;
            *(__half2*)&Sp[(size_t)n * NHW + m] =
                __floats2half2_rn(acc[mi][ni][0] * sc, acc[mi][ni][1] * sc);
            *(__half2*)&Sp[(size_t)(n + 8) * NHW + m] =
                __floats2half2_rn(acc[mi][ni][2] * sc, acc[mi][ni][3] * sc);
        }
    }
}

// ---------------- 5) softmax + 8-bit quantize (f16 in, bf16 codes out) ----------------
__global__ void __launch_bounds__(256) softmax_kernel(const float* __restrict__ dwp,
                                                      const float* __restrict__ zwp) {
    size_t row = blockIdx.x;
    const __half* s = g_S + row * NHW;
    __nv_bfloat16* a = g_a + row * NHW;
    int tid = threadIdx.x;
    float v[16];
    #pragma unroll
    for (int j = 0; j < 2; j++) {
        uint4 t = *(const uint4*)&s[(j * 256 + tid) * 8];
        const __half2* hp = (const __half2*)&t;
        #pragma unroll
        for (int l = 0; l < 4; l++) {
            float2 f = __half22float2(hp[l]);
            v[j * 8 + 2 * l]     = f.x;
            v[j * 8 + 2 * l + 1] = f.y;
        }
    }
    float mx = -3.4e38f;
    #pragma unroll
    for (int i = 0; i < 16; i++) mx = fmaxf(mx, v[i]);
    __shared__ float red[8];
    #pragma unroll
    for (int o = 16; o; o >>= 1) mx = fmaxf(mx, __shfl_xor_sync(0xffffffffu, mx, o));
    if ((tid & 31) == 0) red[tid >> 5] = mx;
    __syncthreads();
    mx = red[0];
    #pragma unroll
    for (int k = 1; k < 8; k++) mx = fmaxf(mx, red[k]);
    __syncthreads();
    float sum = 0.f;
    #pragma unroll
    for (int i = 0; i < 16; i++) { v[i] = __expf(v[i] - mx); sum += v[i]; }
    #pragma unroll
    for (int o = 16; o; o >>= 1) sum += __shfl_xor_sync(0xffffffffu, sum, o);
    if ((tid & 31) == 0) red[tid >> 5] = sum;
    __syncthreads();
    sum = 0.f;
    #pragma unroll
    for (int k = 0; k < 8; k++) sum += red[k];
    float rinv = 1.0f / sum;
    float dinv = 1.0f / dwp[0], zw = zwp[0];
    #pragma unroll
    for (int j = 0; j < 2; j++) {
        union { __nv_bfloat16 h[8]; uint4 u; } pk;
        #pragma unroll
        for (int l = 0; l < 8; l++)
            pk.h[l] = __float2bfloat16(fq_code(v[j * 8 + l] * rinv, dinv, zw));
        *(uint4*)&a[(j * 256 + tid) * 8] = pk.u;
    }
}

// ---------------- 6) gemm2: hoT = a . v^T, emit split hi/lo (128x128, KTG=64) ----------------
__global__ void __launch_bounds__(256) gemm2_kernel(const float* __restrict__ dvp,
                                                    const float* __restrict__ dwp) {
    extern __shared__ __nv_bfloat16 ds[];
    __nv_bfloat16 (*As)[128][SPG] = (__nv_bfloat16 (*)[128][SPG])ds;
    __nv_bfloat16 (*Bs)[128][SPG] = (__nv_bfloat16 (*)[128][SPG])(ds + 2 * 128 * SPG);

    int b = blockIdx.z, n0 = blockIdx.x * 128, c0 = blockIdx.y * 128;
    const __nv_bfloat16* A  = g_a + (size_t)b * NHW * NHW;   // [n][m]
    const __nv_bfloat16* Bm = g_v + (size_t)b * NC * NHW;    // [c][m]
    int tid = threadIdx.x, warp = tid >> 5, lane = tid & 31;
    int g = lane >> 2, ti = lane & 3, wr = warp & 1, wc = warp >> 1;
    int la  = lane & 15;
    int kA  = ((lane >> 4) & 1) * 8;
    int lb  = (lane & 7) + ((lane >> 4) & 1) * 8;
    int kB  = ((lane >> 3) & 1) * 8;
    float acc[4][4][4] = {};
    #pragma unroll
    for (int u = 0; u < 4; u++) {
        int c = tid + u * 256; int r = c >> 3, q = (c & 7) * 8;
        cp16(&As[0][r][q], &A [(size_t)(n0 + r) * NHW + q]);
        cp16(&Bs[0][r][q], &Bm[(size_t)(c0 + r) * NHW + q]);
    }
    CP_COMMIT();
    const int T = NHW / KTG;  // 64
    for (int t = 0; t < T; t++) {
        if (t + 1 < T) {
            int k0 = (t + 1) * KTG, bi = (t + 1) & 1;
            #pragma unroll
            for (int u = 0; u < 4; u++) {
                int c = tid + u * 256; int r = c >> 3, q = (c & 7) * 8;
                cp16(&As[bi][r][q], &A [(size_t)(n0 + r) * NHW + k0 + q]);
                cp16(&Bs[bi][r][q], &Bm[(size_t)(c0 + r) * NHW + k0 + q]);
            }
            CP_COMMIT(); CP_WAIT1();
        } else CP_WAIT0();
        __syncthreads();
        int bi = t & 1;
        #pragma unroll
        for (int kk = 0; kk < KTG; kk += 16) {
            uint32_t af[4][4], bf[2][4];
            #pragma unroll
            for (int mi = 0; mi < 4; mi++)
                ldsm4(af[mi], &As[bi][wr * 64 + mi * 16 + la][kk + kA]);
            #pragma unroll
            for (int nj = 0; nj < 2; nj++)
                ldsm4(bf[nj], &Bs[bi][wc * 32 + nj * 16 + lb][kk + kB]);
            #pragma unroll
            for (int mi = 0; mi < 4; mi++)
                #pragma unroll
                for (int ni = 0; ni < 4; ni++)
                    mma16816(acc[mi][ni], af[mi], &bf[ni >> 1][(ni & 1) * 2]);
        }
        __syncthreads();
    }
    float sc = dvp[0] * dwp[0];
    __nv_bfloat16* Oh = g_hoT_hi + (size_t)b * NHW * NC;
    __nv_bfloat16* Ol = g_hoT_lo + (size_t)b * NHW * NC;
    #pragma unroll
    for (int mi = 0; mi < 4; mi++) {
        int n = n0 + wr * 64 + mi * 16 + g;
        #pragma unroll
        for (int ni = 0; ni < 4; ni++) {
            int c = c0 + wc * 32 + ni * 8 + 2 * ti;
            #pragma unroll
            for (int half = 0; half < 2; half++) {
                float v0 = acc[mi][ni][2 * half] * sc;
                float v1 = acc[mi][ni][2 * half + 1] * sc;
                __nv_bfloat16 h0 = __float2bfloat16(v0);
                __nv_bfloat16 h1 = __float2bfloat16(v1);
                union { __nv_bfloat16 h[2]; uint32_t u; } ph, pl;
                ph.h[0] = h0; ph.h[1] = h1;
                pl.h[0] = __float2bfloat16(v0 - __bfloat162float(h0));
                pl.h[1] = __float2bfloat16(v1 - __bfloat162float(h1));
                size_t off = (size_t)(n + 8 * half) * NC + c;
                *(uint32_t*)&Oh[off] = ph.u;
                *(uint32_t*)&Ol[off] = pl.u;
            }
        }
    }
}

// ---------------- 7) proj: split-bf16 mma + bias + residual (double-buffered) ----------------
__global__ void __launch_bounds__(256) proj_kernel(const float* __restrict__ x,
                                                   const float* __restrict__ bias,
                                                   float* __restrict__ out) {
    extern __shared__ char qsm[];
    __nv_bfloat16 (*tiles)[4][128][SP] = (__nv_bfloat16 (*)[4][128][SP])qsm;
    float (*tf)[132] = (float (*)[132])qsm;   // epilogue alias (64*132*4 = 33792 B)

    int b = blockIdx.z;
    int n0 = blockIdx.x * 128, o0 = blockIdx.y * 128;
    const __nv_bfloat16* Wh = g_w_hi + 3 * NC * NC;
    const __nv_bfloat16* Wl = g_w_lo + 3 * NC * NC;
    const __nv_bfloat16* Ahg = g_hoT_hi + (size_t)b * NHW * NC;
    const __nv_bfloat16* Alg = g_hoT_lo + (size_t)b * NHW * NC;

    int tid = threadIdx.x, warp = tid >> 5, lane = tid & 31;
    int g = lane >> 2, ti = lane & 3, wr = warp & 1, wc = warp >> 1;
    int la  = lane & 15;
    int kA  = ((lane >> 4) & 1) * 8;
    int lb  = (lane & 7) + ((lane >> 4) & 1) * 8;
    int kB  = ((lane >> 3) & 1) * 8;
    float acc[4][4][4] = {};

    #define PROJ_LOAD(st, k0)                                                       \
        do {                                                                        \
            _Pragma("unroll")                                                       \
            for (int u = 0; u < 2; u++) {                                           \
                int c = tid + u * 256; int r = c >> 2, q = (c & 3) * 8;             \
                cp16(&tiles[st][0][r][q], &Ahg[(size_t)(n0 + r) * NC + (k0) + q]);  \
                cp16(&tiles[st][1][r][q], &Alg[(size_t)(n0 + r) * NC + (k0) + q]);  \
                cp16(&tiles[st][2][r][q], &Wh[(o0 + r) * NC + (k0) + q]);           \
                cp16(&tiles[st][3][r][q], &Wl[(o0 + r) * NC + (k0) + q]);           \
            }                                                                       \
        } while (0)

    PROJ_LOAD(0, 0);
    CP_COMMIT();
    const int T = NC / KT;   // 8
    for (int t = 0; t < T; t++) {
        if (t + 1 < T) {
            PROJ_LOAD((t + 1) & 1, (t + 1) * KT);
            CP_COMMIT(); CP_WAIT1();
        } else CP_WAIT0();
        __syncthreads();
        int bi = t & 1;
        #pragma unroll
        for (int kk = 0; kk < KT; kk += 16) {
            uint32_t ah[4][4], al[4][4], bh[2][4], bl[2][4];
            #pragma unroll
            for (int mi = 0; mi < 4; mi++) {
                int r = wr * 64 + mi * 16 + la;
                ldsm4(ah[mi], &tiles[bi][0][r][kk + kA]);
                ldsm4(al[mi], &tiles[bi][1][r][kk + kA]);
            }
            #pragma unroll
            for (int nj = 0; nj < 2; nj++) {
                int c = wc * 32 + nj * 16 + lb;
                ldsm4(bh[nj], &tiles[bi][2][c][kk + kB]);
                ldsm4(bl[nj], &tiles[bi][3][c][kk + kB]);
            }
            #pragma unroll
            for (int mi = 0; mi < 4; mi++)
                #pragma unroll
                for (int ni = 0; ni < 4; ni++) {
                    mma16816(acc[mi][ni], ah[mi], &bh[ni >> 1][(ni & 1) * 2]);
                    mma16816(acc[mi][ni], ah[mi], &bl[ni >> 1][(ni & 1) * 2]);
                    mma16816(acc[mi][ni], al[mi], &bh[ni >> 1][(ni & 1) * 2]);
                }
        }
        __syncthreads();
    }
    #undef PROJ_LOAD

    #pragma unroll
    for (int hp = 0; hp < 2; hp++) {
        if ((wc >> 1) == hp) {
            #pragma unroll
            for (int mi = 0; mi < 4; mi++) {
                int nl = wr * 64 + mi * 16 + g;
                #pragma unroll
                for (int ni = 0; ni < 4; ni++) {
                    int ol = (wc & 1) * 32 + ni * 8 + 2 * ti;
                    tf[ol    ][nl    ] = acc[mi][ni][0];
                    tf[ol + 1][nl    ] = acc[mi][ni][1];
                    tf[ol    ][nl + 8] = acc[mi][ni][2];
                    tf[ol + 1][nl + 8] = acc[mi][ni][3];
                }
            }
        }
        __syncthreads();
        int r = tid >> 2, qn = (tid & 3) * 32;
        int o = o0 + hp * 64 + r;
        float bo = bias[o];
        size_t bse = ((size_t)b * NC + o) * NHW + n0 + qn;
        #pragma unroll
        for (int j = 0; j < 32; j += 4) {
            float4 xv = *(const float4*)&x[bse + j];
            float4 tv = *(const float4*)&tf[r][qn + j];
            float4 rv;
            rv.x = xv.x + tv.x + bo; rv.y = xv.y + tv.y + bo;
            rv.z = xv.z + tv.z + bo; rv.w = xv.w + tv.w + bo;
            *(float4*)&out[bse + j] = rv;
        }
        __syncthreads();
    }
}

// ---------------- launch ----------------
extern "C" void kernel_launch(void* const* d_in, const int* in_sizes, int n_in,
                              void* d_out, int out_size) {
    const float* x      = (const float*)d_in[0];
    const float* gns    = (const float*)d_in[1];
    const float* gnb    = (const float*)d_in[2];
    const float* wq     = (const float*)d_in[3];
    const float* bq     = (const float*)d_in[4];
    const float* wk     = (const float*)d_in[5];
    const float* bk     = (const float*)d_in[6];
    const float* wv     = (const float*)d_in[7];
    const float* bv     = (const float*)d_in[8];
    const float* wproj  = (const float*)d_in[9];
    const float* bproj  = (const float*)d_in[10];
    const float* dq     = (const float*)d_in[11];
    const float* zq     = (const float*)d_in[12];
    const float* dk     = (const float*)d_in[13];
    const float* zk     = (const float*)d_in[14];
    const float* dv     = (const float*)d_in[15];
    const float* zv     = (const float*)d_in[16];
    const float* dw     = (const float*)d_in[17];
    const float* zw     = (const float*)d_in[18];
    float* out = (float*)d_out;

    const int GSMEM  = 4 * 128 * SPG * 2;   // 73728 B (gemm1/gemm2)
    const int CSMEM  = 2 * 4 * 128 * SP * 2; // 81920 B (qkv/proj, 2-stage)
    cudaFuncSetAttribute(gemm1_kernel, cudaFuncAttributeMaxDynamicSharedMemorySize, GSMEM);
    cudaFuncSetAttribute(gemm2_kernel, cudaFuncAttributeMaxDynamicSharedMemorySize, GSMEM);
    cudaFuncSetAttribute(qkv_kernel,   cudaFuncAttributeMaxDynamicSharedMemorySize, CSMEM);
    cudaFuncSetAttribute(proj_kernel,  cudaFuncAttributeMaxDynamicSharedMemorySize, CSMEM);

    gn_kernel<<<NB * 32, 256>>>(x, gns, gnb);
    wsplit_kernel<<<256, 256>>>(wq, wk, wv, wproj);
    qkv_kernel<<<dim3(NHW / 128, NC / 128, NB * 3), 256, CSMEM>>>(
        bq, bk, bv, dq, zq, dk, zk, dv, zv);
    gemm1_kernel<<<dim3(NHW / 128, NHW / 128, NB), 256, GSMEM>>>(dq, dk);
    softmax_kernel<<<NB * NHW, 256>>>(dw, zw);
    gemm2_kernel<<<dim3(NHW / 128, NC / 128, NB), 256, GSMEM>>>(dv, dw);
    proj_kernel<<<dim3(NHW / 128, NC / 128, NB), 256, CSMEM>>>(x, bproj, out);
}

// round 15
// speedup vs baseline: 2.2032x; 1.0205x over previous
#include <cuda_runtime.h>
#include <cuda_bf16.h>
#include <cuda_fp16.h>
#include <cstdint>

#define NB 4
#define NC 256
#define NHW 4096
#define KT 32
#define SP 40    // padded smem row stride (bf16 elems) for conv kernels
#define KTG 64   // gemm1/gemm2 k-tile
#define SPG 72   // padded row stride for KTG tiles (144B, conflict-free)

// ---------------- scratch ----------------
__device__ __nv_bfloat16 g_hT_hi[NB*NHW*NC];
__device__ __nv_bfloat16 g_hT_lo[NB*NHW*NC];
__device__ __nv_bfloat16 g_w_hi[4*NC*NC];   // q,k,v,proj
__device__ __nv_bfloat16 g_w_lo[4*NC*NC];
__device__ __nv_bfloat16 g_q[NB*NHW*NC];    // quantized q codes [b][n][c]
__device__ __nv_bfloat16 g_k[NB*NHW*NC];    // quantized k codes [b][m][c]
__device__ __nv_bfloat16 g_v[NB*NC*NHW];    // quantized v codes [b][c][m]
__device__ __half        g_S[(size_t)NB*NHW*NHW];  // logits (f16)
__device__ __nv_bfloat16 g_a[(size_t)NB*NHW*NHW];  // quantized attn codes [b][n][m]
__device__ __nv_bfloat16 g_hoT_hi[NB*NHW*NC];
__device__ __nv_bfloat16 g_hoT_lo[NB*NHW*NC];

// ---------------- helpers ----------------
__device__ __forceinline__ void mma16816(float d[4], const uint32_t a[4], const uint32_t b[2]) {
    asm volatile(
        "mma.sync.aligned.m16n8k16.row.col.f32.bf16.bf16.f32 "
        "{%0,%1,%2,%3},{%4,%5,%6,%7},{%8,%9},{%0,%1,%2,%3};\n"
        : "+f"(d[0]), "+f"(d[1]), "+f"(d[2]), "+f"(d[3])
        : "r"(a[0]), "r"(a[1]), "r"(a[2]), "r"(a[3]), "r"(b[0]), "r"(b[1]));
}
__device__ __forceinline__ void ldsm4(uint32_t r[4], const void* p) {
    uint32_t a = (uint32_t)__cvta_generic_to_shared(p);
    asm volatile("ldmatrix.sync.aligned.m8n8.x4.shared.b16 {%0,%1,%2,%3},[%4];\n"
        : "=r"(r[0]), "=r"(r[1]), "=r"(r[2]), "=r"(r[3]) : "r"(a));
}
__device__ __forceinline__ void cp16(void* s, const void* g) {
    uint32_t sa = (uint32_t)__cvta_generic_to_shared(s);
    asm volatile("cp.async.cg.shared.global [%0],[%1],16;\n" :: "r"(sa), "l"(g));
}
#define CP_COMMIT() asm volatile("cp.async.commit_group;\n")
#define CP_WAIT0()  asm volatile("cp.async.wait_group 0;\n")
#define CP_WAIT1()  asm volatile("cp.async.wait_group 1;\n")

__device__ __forceinline__ float fq_code(float v, float dinv, float zp) {
    float q = rintf(v * dinv) + zp;
    q = fminf(fmaxf(q, 0.0f), 255.0f);
    return q - zp;
}

// ---------------- 1) GroupNorm -> hT hi/lo [b][n][c] ----------------
__global__ void __launch_bounds__(256) gn_kernel(const float* __restrict__ x,
                                                 const float* __restrict__ gam,
                                                 const float* __restrict__ bet) {
    int b = blockIdx.x >> 5, gr = blockIdx.x & 31;
    const float* xp = x + ((size_t)(b * NC) + gr * 8) * NHW;
    int tid = threadIdx.x;
    const int Nf4 = 8 * NHW / 4;
    const float4* x4 = (const float4*)xp;
    float s = 0.f, ss = 0.f;
    for (int i = tid; i < Nf4; i += 256) {
        float4 v = x4[i];
        s  += v.x + v.y + v.z + v.w;
        ss += v.x * v.x + v.y * v.y + v.z * v.z + v.w * v.w;
    }
    __shared__ float rs[8], rss[8], s_sc[8], s_sh[8];
    #pragma unroll
    for (int o = 16; o; o >>= 1) {
        s  += __shfl_down_sync(0xffffffffu, s, o);
        ss += __shfl_down_sync(0xffffffffu, ss, o);
    }
    if ((tid & 31) == 0) { rs[tid >> 5] = s; rss[tid >> 5] = ss; }
    __syncthreads();
    float ts = 0.f, tss = 0.f;
    #pragma unroll
    for (int k = 0; k < 8; k++) { ts += rs[k]; tss += rss[k]; }
    const float inv = 1.0f / (float)(8 * NHW);
    float mu = ts * inv;
    float var = tss * inv - mu * mu;
    float rstd = 1.0f / sqrtf(var + 1e-6f);
    if (tid < 8) {
        float gm = gam[gr * 8 + tid];
        s_sc[tid] = gm * rstd;
        s_sh[tid] = bet[gr * 8 + tid] - mu * gm * rstd;
    }
    __syncthreads();
    __nv_bfloat16* Hh = g_hT_hi + (size_t)b * NHW * NC + gr * 8;
    __nv_bfloat16* Hl = g_hT_lo + (size_t)b * NHW * NC + gr * 8;
    for (int n = tid; n < NHW; n += 256) {
        union { __nv_bfloat16 h[8]; uint4 u; } ph, pl;
        #pragma unroll
        for (int c = 0; c < 8; c++) {
            float v = xp[(size_t)c * NHW + n] * s_sc[c] + s_sh[c];
            __nv_bfloat16 hi = __float2bfloat16(v);
            ph.h[c] = hi;
            pl.h[c] = __float2bfloat16(v - __bfloat162float(hi));
        }
        *(uint4*)&Hh[(size_t)n * NC] = ph.u;
        *(uint4*)&Hl[(size_t)n * NC] = pl.u;
    }
}

// ---------------- 2) weight split ----------------
__global__ void __launch_bounds__(256) wsplit_kernel(const float* __restrict__ wq,
                                                     const float* __restrict__ wk,
                                                     const float* __restrict__ wv,
                                                     const float* __restrict__ wp) {
    int idx = blockIdx.x * 256 + threadIdx.x;
    const float* ws[4] = {wq, wk, wv, wp};
    #pragma unroll
    for (int m = 0; m < 4; m++) {
        float v = ws[m][idx];
        __nv_bfloat16 hi = __float2bfloat16(v);
        g_w_hi[m * NC * NC + idx] = hi;
        g_w_lo[m * NC * NC + idx] = __float2bfloat16(v - __bfloat162float(hi));
    }
}

// ---------------- 3) QK conv: split-bf16 mma + quantize (double-buffered) ----------------
__global__ void __launch_bounds__(256) qk_kernel(
    const float* __restrict__ bq, const float* __restrict__ bk,
    const float* __restrict__ dqp, const float* __restrict__ zqp,
    const float* __restrict__ dkp, const float* __restrict__ zkp) {
    extern __shared__ char qsm[];
    __nv_bfloat16 (*tiles)[4][128][SP] = (__nv_bfloat16 (*)[4][128][SP])qsm;

    int z = blockIdx.z;
    int b = z >> 1, which = z & 1;
    const __nv_bfloat16* Wh = g_w_hi + which * NC * NC;
    const __nv_bfloat16* Wl = g_w_lo + which * NC * NC;
    const float* bias = which == 0 ? bq : bk;
    float d  = which == 0 ? dqp[0] : dkp[0];
    float zp = which == 0 ? zqp[0] : zkp[0];
    int n0 = blockIdx.x * 128, o0 = blockIdx.y * 128;
    const __nv_bfloat16* Ahg = g_hT_hi + (size_t)b * NHW * NC;
    const __nv_bfloat16* Alg = g_hT_lo + (size_t)b * NHW * NC;

    int tid = threadIdx.x, warp = tid >> 5, lane = tid & 31;
    int g = lane >> 2, ti = lane & 3, wr = warp & 1, wc = warp >> 1;
    int la  = lane & 15;
    int kA  = ((lane >> 4) & 1) * 8;
    int lb  = (lane & 7) + ((lane >> 4) & 1) * 8;
    int kB  = ((lane >> 3) & 1) * 8;
    float acc[4][4][4] = {};

    #define QK_LOAD(st, k0)                                                         \
        do {                                                                        \
            _Pragma("unroll")                                                       \
            for (int u = 0; u < 2; u++) {                                           \
                int c = tid + u * 256; int r = c >> 2, q = (c & 3) * 8;             \
                cp16(&tiles[st][0][r][q], &Ahg[(size_t)(n0 + r) * NC + (k0) + q]);  \
                cp16(&tiles[st][1][r][q], &Alg[(size_t)(n0 + r) * NC + (k0) + q]);  \
                cp16(&tiles[st][2][r][q], &Wh[(o0 + r) * NC + (k0) + q]);           \
                cp16(&tiles[st][3][r][q], &Wl[(o0 + r) * NC + (k0) + q]);           \
            }                                                                       \
        } while (0)

    QK_LOAD(0, 0);
    CP_COMMIT();
    const int T = NC / KT;   // 8
    for (int t = 0; t < T; t++) {
        if (t + 1 < T) {
            QK_LOAD((t + 1) & 1, (t + 1) * KT);
            CP_COMMIT(); CP_WAIT1();
        } else CP_WAIT0();
        __syncthreads();
        int bi = t & 1;
        #pragma unroll
        for (int kk = 0; kk < KT; kk += 16) {
            uint32_t ah[4][4], al[4][4], bh[2][4], bl[2][4];
            #pragma unroll
            for (int mi = 0; mi < 4; mi++) {
                int r = wr * 64 + mi * 16 + la;
                ldsm4(ah[mi], &tiles[bi][0][r][kk + kA]);
                ldsm4(al[mi], &tiles[bi][1][r][kk + kA]);
            }
            #pragma unroll
            for (int nj = 0; nj < 2; nj++) {
                int c = wc * 32 + nj * 16 + lb;
                ldsm4(bh[nj], &tiles[bi][2][c][kk + kB]);
                ldsm4(bl[nj], &tiles[bi][3][c][kk + kB]);
            }
            #pragma unroll
            for (int mi = 0; mi < 4; mi++)
                #pragma unroll
                for (int ni = 0; ni < 4; ni++) {
                    mma16816(acc[mi][ni], ah[mi], &bh[ni >> 1][(ni & 1) * 2]);
                    mma16816(acc[mi][ni], ah[mi], &bl[ni >> 1][(ni & 1) * 2]);
                    mma16816(acc[mi][ni], al[mi], &bh[ni >> 1][(ni & 1) * 2]);
                }
        }
        __syncthreads();
    }
    #undef QK_LOAD

    float dinv = 1.0f / d;
    __nv_bfloat16* Out = (which == 0 ? g_q : g_k) + (size_t)b * NHW * NC;
    #pragma unroll
    for (int mi = 0; mi < 4; mi++) {
        int n = n0 + wr * 64 + mi * 16 + g;
        #pragma unroll
        for (int ni = 0; ni < 4; ni++) {
            int o = o0 + wc * 32 + ni * 8 + 2 * ti;
            float b0 = bias[o], b1 = bias[o + 1];
            union { __nv_bfloat16 h[2]; uint32_t u; } p0, p1;
            p0.h[0] = __float2bfloat16(fq_code(acc[mi][ni][0] + b0, dinv, zp));
            p0.h[1] = __float2bfloat16(fq_code(acc[mi][ni][1] + b1, dinv, zp));
            p1.h[0] = __float2bfloat16(fq_code(acc[mi][ni][2] + b0, dinv, zp));
            p1.h[1] = __float2bfloat16(fq_code(acc[mi][ni][3] + b1, dinv, zp));
            *(uint32_t*)&Out[(size_t)n * NC + o]       = p0.u;
            *(uint32_t*)&Out[(size_t)(n + 8) * NC + o] = p1.u;
        }
    }
}

// ---------------- 4) FUSED: v-conv (first 256 blocks) + gemm1 (next 4096 blocks) ----------------
__global__ void __launch_bounds__(256) g1v_kernel(
    const float* __restrict__ dqp, const float* __restrict__ dkp,
    const float* __restrict__ bv, const float* __restrict__ dvp,
    const float* __restrict__ zvp) {
    extern __shared__ char dsmc[];
    int bid = blockIdx.x;
    int tid = threadIdx.x, warp = tid >> 5, lane = tid & 31;
    int g = lane >> 2, ti = lane & 3, wr = warp & 1, wc = warp >> 1;
    int la  = lane & 15;
    int kA  = ((lane >> 4) & 1) * 8;
    int lb  = (lane & 7) + ((lane >> 4) & 1) * 8;
    int kB  = ((lane >> 3) & 1) * 8;

    if (bid < 256) {
        // ---- v-conv body (split-bf16, double-buffered) ----
        __nv_bfloat16 (*tiles)[4][128][SP] = (__nv_bfloat16 (*)[4][128][SP])dsmc;
        __nv_bfloat16 (*tb)[136] = (__nv_bfloat16 (*)[136])dsmc;
        int n0 = (bid & 31) * 128;
        int o0 = ((bid >> 5) & 1) * 128;
        int b  = bid >> 6;
        const __nv_bfloat16* Wh = g_w_hi + 2 * NC * NC;
        const __nv_bfloat16* Wl = g_w_lo + 2 * NC * NC;
        const __nv_bfloat16* Ahg = g_hT_hi + (size_t)b * NHW * NC;
        const __nv_bfloat16* Alg = g_hT_lo + (size_t)b * NHW * NC;
        float d = dvp[0], zp = zvp[0];
        float acc[4][4][4] = {};

        #define V_LOAD(st, k0)                                                          \
            do {                                                                        \
                _Pragma("unroll")                                                       \
                for (int u = 0; u < 2; u++) {                                           \
                    int c = tid + u * 256; int r = c >> 2, q = (c & 3) * 8;             \
                    cp16(&tiles[st][0][r][q], &Ahg[(size_t)(n0 + r) * NC + (k0) + q]);  \
                    cp16(&tiles[st][1][r][q], &Alg[(size_t)(n0 + r) * NC + (k0) + q]);  \
                    cp16(&tiles[st][2][r][q], &Wh[(o0 + r) * NC + (k0) + q]);           \
                    cp16(&tiles[st][3][r][q], &Wl[(o0 + r) * NC + (k0) + q]);           \
                }                                                                       \
            } while (0)

        V_LOAD(0, 0);
        CP_COMMIT();
        const int T = NC / KT;   // 8
        for (int t = 0; t < T; t++) {
            if (t + 1 < T) {
                V_LOAD((t + 1) & 1, (t + 1) * KT);
                CP_COMMIT(); CP_WAIT1();
            } else CP_WAIT0();
            __syncthreads();
            int bi = t & 1;
            #pragma unroll
            for (int kk = 0; kk < KT; kk += 16) {
                uint32_t ah[4][4], al[4][4], bh[2][4], bl[2][4];
                #pragma unroll
                for (int mi = 0; mi < 4; mi++) {
                    int r = wr * 64 + mi * 16 + la;
                    ldsm4(ah[mi], &tiles[bi][0][r][kk + kA]);
                    ldsm4(al[mi], &tiles[bi][1][r][kk + kA]);
                }
                #pragma unroll
                for (int nj = 0; nj < 2; nj++) {
                    int c = wc * 32 + nj * 16 + lb;
                    ldsm4(bh[nj], &tiles[bi][2][c][kk + kB]);
                    ldsm4(bl[nj], &tiles[bi][3][c][kk + kB]);
                }
                #pragma unroll
                for (int mi = 0; mi < 4; mi++)
                    #pragma unroll
                    for (int ni = 0; ni < 4; ni++) {
                        mma16816(acc[mi][ni], ah[mi], &bh[ni >> 1][(ni & 1) * 2]);
                        mma16816(acc[mi][ni], ah[mi], &bl[ni >> 1][(ni & 1) * 2]);
                        mma16816(acc[mi][ni], al[mi], &bh[ni >> 1][(ni & 1) * 2]);
                    }
            }
            __syncthreads();
        }
        #undef V_LOAD

        float dinv = 1.0f / d;
        #pragma unroll
        for (int mi = 0; mi < 4; mi++) {
            int nl = wr * 64 + mi * 16 + g;
            #pragma unroll
            for (int ni = 0; ni < 4; ni++) {
                int ol = wc * 32 + ni * 8 + 2 * ti;
                float b0 = bv[o0 + ol], b1 = bv[o0 + ol + 1];
                tb[ol    ][nl    ] = __float2bfloat16(fq_code(acc[mi][ni][0] + b0, dinv, zp));
                tb[ol + 1][nl    ] = __float2bfloat16(fq_code(acc[mi][ni][1] + b1, dinv, zp));
                tb[ol    ][nl + 8] = __float2bfloat16(fq_code(acc[mi][ni][2] + b0, dinv, zp));
                tb[ol + 1][nl + 8] = __float2bfloat16(fq_code(acc[mi][ni][3] + b1, dinv, zp));
            }
        }
        __syncthreads();
        int r = tid >> 1, half = (tid & 1) * 64;
        #pragma unroll
        for (int j = 0; j < 64; j += 8)
            *(uint4*)&g_v[((size_t)b * NC + o0 + r) * NHW + n0 + half + j] =
                *(uint4*)&tb[r][half + j];
    } else {
        // ---- gemm1 body: S = q . k^T (KTG=64, f16 out) ----
        int gid = bid - 256;
        int m0 = (gid & 31) * 128;
        int n0 = ((gid >> 5) & 31) * 128;
        int b  = gid >> 10;
        __nv_bfloat16 (*As)[128][SPG] = (__nv_bfloat16 (*)[128][SPG])dsmc;
        __nv_bfloat16 (*Bs)[128][SPG] = (__nv_bfloat16 (*)[128][SPG])(dsmc + 2 * 128 * SPG * 2);
        const __nv_bfloat16* A  = g_q + (size_t)b * NHW * NC;
        const __nv_bfloat16* Bm = g_k + (size_t)b * NHW * NC;
        float acc[4][4][4] = {};
        #pragma unroll
        for (int u = 0; u < 4; u++) {
            int c = tid + u * 256; int r = c >> 3, q = (c & 7) * 8;
            cp16(&As[0][r][q], &A [(size_t)(n0 + r) * NC + q]);
            cp16(&Bs[0][r][q], &Bm[(size_t)(m0 + r) * NC + q]);
        }
        CP_COMMIT();
        const int T = NC / KTG;   // 4
        for (int t = 0; t < T; t++) {
            if (t + 1 < T) {
                int k0 = (t + 1) * KTG, bi = (t + 1) & 1;
                #pragma unroll
                for (int u = 0; u < 4; u++) {
                    int c = tid + u * 256; int r = c >> 3, q = (c & 7) * 8;
                    cp16(&As[bi][r][q], &A [(size_t)(n0 + r) * NC + k0 + q]);
                    cp16(&Bs[bi][r][q], &Bm[(size_t)(m0 + r) * NC + k0 + q]);
                }
                CP_COMMIT(); CP_WAIT1();
            } else CP_WAIT0();
            __syncthreads();
            int bi = t & 1;
            #pragma unroll
            for (int kk = 0; kk < KTG; kk += 16) {
                uint32_t af[4][4], bf[2][4];
                #pragma unroll
                for (int mi = 0; mi < 4; mi++)
                    ldsm4(af[mi], &As[bi][wr * 64 + mi * 16 + la][kk + kA]);
                #pragma unroll
                for (int nj = 0; nj < 2; nj++)
                    ldsm4(bf[nj], &Bs[bi][wc * 32 + nj * 16 + lb][kk + kB]);
                #pragma unroll
                for (int mi = 0; mi < 4; mi++)
                    #pragma unroll
                    for (int ni = 0; ni < 4; ni++)
                        mma16816(acc[mi][ni], af[mi], &bf[ni >> 1][(ni & 1) * 2]);
            }
            __syncthreads();
        }
        float sc = dqp[0] * dkp[0] * 0.0625f;
        __half* Sp = g_S + (size_t)b * NHW * NHW;
        #pragma unroll
        for (int mi = 0; mi < 4; mi++) {
            int n = n0 + wr * 64 + mi * 16 + g;
            #pragma unroll
            for (int ni = 0; ni < 4; ni++) {
                int m = m0 + wc * 32 + ni * 8 + 2 * ti;
                *(__half2*)&Sp[(size_t)n * NHW + m] =
                    __floats2half2_rn(acc[mi][ni][0] * sc, acc[mi][ni][1] * sc);
                *(__half2*)&Sp[(size_t)(n + 8) * NHW + m] =
                    __floats2half2_rn(acc[mi][ni][2] * sc, acc[mi][ni][3] * sc);
            }
        }
    }
}

// ---------------- 5) softmax + 8-bit quantize (f16 in, bf16 codes out) ----------------
__global__ void __launch_bounds__(256) softmax_kernel(const float* __restrict__ dwp,
                                                      const float* __restrict__ zwp) {
    size_t row = blockIdx.x;
    const __half* s = g_S + row * NHW;
    __nv_bfloat16* a = g_a + row * NHW;
    int tid = threadIdx.x;
    float v[16];
    #pragma unroll
    for (int j = 0; j < 2; j++) {
        uint4 t = *(const uint4*)&s[(j * 256 + tid) * 8];
        const __half2* hp = (const __half2*)&t;
        #pragma unroll
        for (int l = 0; l < 4; l++) {
            float2 f = __half22float2(hp[l]);
            v[j * 8 + 2 * l]     = f.x;
            v[j * 8 + 2 * l + 1] = f.y;
        }
    }
    float mx = -3.4e38f;
    #pragma unroll
    for (int i = 0; i < 16; i++) mx = fmaxf(mx, v[i]);
    __shared__ float red[8];
    #pragma unroll
    for (int o = 16; o; o >>= 1) mx = fmaxf(mx, __shfl_xor_sync(0xffffffffu, mx, o));
    if ((tid & 31) == 0) red[tid >> 5] = mx;
    __syncthreads();
    mx = red[0];
    #pragma unroll
    for (int k = 1; k < 8; k++) mx = fmaxf(mx, red[k]);
    __syncthreads();
    float sum = 0.f;
    #pragma unroll
    for (int i = 0; i < 16; i++) { v[i] = __expf(v[i] - mx); sum += v[i]; }
    #pragma unroll
    for (int o = 16; o; o >>= 1) sum += __shfl_xor_sync(0xffffffffu, sum, o);
    if ((tid & 31) == 0) red[tid >> 5] = sum;
    __syncthreads();
    sum = 0.f;
    #pragma unroll
    for (int k = 0; k < 8; k++) sum += red[k];
    float rinv = 1.0f / sum;
    float dinv = 1.0f / dwp[0], zw = zwp[0];
    #pragma unroll
    for (int j = 0; j < 2; j++) {
        union { __nv_bfloat16 h[8]; uint4 u; } pk;
        #pragma unroll
        for (int l = 0; l < 8; l++)
            pk.h[l] = __float2bfloat16(fq_code(v[j * 8 + l] * rinv, dinv, zw));
        *(uint4*)&a[(j * 256 + tid) * 8] = pk.u;
    }
}

// ---------------- 6) gemm2: hoT = a . v^T, emit split hi/lo (128x128, KTG=64) ----------------
__global__ void __launch_bounds__(256) gemm2_kernel(const float* __restrict__ dvp,
                                                    const float* __restrict__ dwp) {
    extern __shared__ __nv_bfloat16 ds[];
    __nv_bfloat16 (*As)[128][SPG] = (__nv_bfloat16 (*)[128][SPG])ds;
    __nv_bfloat16 (*Bs)[128][SPG] = (__nv_bfloat16 (*)[128][SPG])(ds + 2 * 128 * SPG);

    int b = blockIdx.z, n0 = blockIdx.x * 128, c0 = blockIdx.y * 128;
    const __nv_bfloat16* A  = g_a + (size_t)b * NHW * NHW;   // [n][m]
    const __nv_bfloat16* Bm = g_v + (size_t)b * NC * NHW;    // [c][m]
    int tid = threadIdx.x, warp = tid >> 5, lane = tid & 31;
    int g = lane >> 2, ti = lane & 3, wr = warp & 1, wc = warp >> 1;
    int la  = lane & 15;
    int kA  = ((lane >> 4) & 1) * 8;
    int lb  = (lane & 7) + ((lane >> 4) & 1) * 8;
    int kB  = ((lane >> 3) & 1) * 8;
    float acc[4][4][4] = {};
    #pragma unroll
    for (int u = 0; u < 4; u++) {
        int c = tid + u * 256; int r = c >> 3, q = (c & 7) * 8;
        cp16(&As[0][r][q], &A [(size_t)(n0 + r) * NHW + q]);
        cp16(&Bs[0][r][q], &Bm[(size_t)(c0 + r) * NHW + q]);
    }
    CP_COMMIT();
    const int T = NHW / KTG;  // 64
    for (int t = 0; t < T; t++) {
        if (t + 1 < T) {
            int k0 = (t + 1) * KTG, bi = (t + 1) & 1;
            #pragma unroll
            for (int u = 0; u < 4; u++) {
                int c = tid + u * 256; int r = c >> 3, q = (c & 7) * 8;
                cp16(&As[bi][r][q], &A [(size_t)(n0 + r) * NHW + k0 + q]);
                cp16(&Bs[bi][r][q], &Bm[(size_t)(c0 + r) * NHW + k0 + q]);
            }
            CP_COMMIT(); CP_WAIT1();
        } else CP_WAIT0();
        __syncthreads();
        int bi = t & 1;
        #pragma unroll
        for (int kk = 0; kk < KTG; kk += 16) {
            uint32_t af[4][4], bf[2][4];
            #pragma unroll
            for (int mi = 0; mi < 4; mi++)
                ldsm4(af[mi], &As[bi][wr * 64 + mi * 16 + la][kk + kA]);
            #pragma unroll
            for (int nj = 0; nj < 2; nj++)
                ldsm4(bf[nj], &Bs[bi][wc * 32 + nj * 16 + lb][kk + kB]);
            #pragma unroll
            for (int mi = 0; mi < 4; mi++)
                #pragma unroll
                for (int ni = 0; ni < 4; ni++)
                    mma16816(acc[mi][ni], af[mi], &bf[ni >> 1][(ni & 1) * 2]);
        }
        __syncthreads();
    }
    float sc = dvp[0] * dwp[0];
    __nv_bfloat16* Oh = g_hoT_hi + (size_t)b * NHW * NC;
    __nv_bfloat16* Ol = g_hoT_lo + (size_t)b * NHW * NC;
    #pragma unroll
    for (int mi = 0; mi < 4; mi++) {
        int n = n0 + wr * 64 + mi * 16 + g;
        #pragma unroll
        for (int ni = 0; ni < 4; ni++) {
            int c = c0 + wc * 32 + ni * 8 + 2 * ti;
            #pragma unroll
            for (int half = 0; half < 2; half++) {
                float v0 = acc[mi][ni][2 * half] * sc;
                float v1 = acc[mi][ni][2 * half + 1] * sc;
                __nv_bfloat16 h0 = __float2bfloat16(v0);
                __nv_bfloat16 h1 = __float2bfloat16(v1);
                union { __nv_bfloat16 h[2]; uint32_t u; } ph, pl;
                ph.h[0] = h0; ph.h[1] = h1;
                pl.h[0] = __float2bfloat16(v0 - __bfloat162float(h0));
                pl.h[1] = __float2bfloat16(v1 - __bfloat162float(h1));
                size_t off = (size_t)(n + 8 * half) * NC + c;
                *(uint32_t*)&Oh[off] = ph.u;
                *(uint32_t*)&Ol[off] = pl.u;
            }
        }
    }
}

// ---------------- 7) proj: split-bf16 mma + bias + residual (double-buffered) ----------------
__global__ void __launch_bounds__(256) proj_kernel(const float* __restrict__ x,
                                                   const float* __restrict__ bias,
                                                   float* __restrict__ out) {
    extern __shared__ char qsm[];
    __nv_bfloat16 (*tiles)[4][128][SP] = (__nv_bfloat16 (*)[4][128][SP])qsm;
    float (*tf)[132] = (float (*)[132])qsm;

    int b = blockIdx.z;
    int n0 = blockIdx.x * 128, o0 = blockIdx.y * 128;
    const __nv_bfloat16* Wh = g_w_hi + 3 * NC * NC;
    const __nv_bfloat16* Wl = g_w_lo + 3 * NC * NC;
    const __nv_bfloat16* Ahg = g_hoT_hi + (size_t)b * NHW * NC;
    const __nv_bfloat16* Alg = g_hoT_lo + (size_t)b * NHW * NC;

    int tid = threadIdx.x, warp = tid >> 5, lane = tid & 31;
    int g = lane >> 2, ti = lane & 3, wr = warp & 1, wc = warp >> 1;
    int la  = lane & 15;
    int kA  = ((lane >> 4) & 1) * 8;
    int lb  = (lane & 7) + ((lane >> 4) & 1) * 8;
    int kB  = ((lane >> 3) & 1) * 8;
    float acc[4][4][4] = {};

    #define PROJ_LOAD(st, k0)                                                       \
        do {                                                                        \
            _Pragma("unroll")                                                       \
            for (int u = 0; u < 2; u++) {                                           \
                int c = tid + u * 256; int r = c >> 2, q = (c & 3) * 8;             \
                cp16(&tiles[st][0][r][q], &Ahg[(size_t)(n0 + r) * NC + (k0) + q]);  \
                cp16(&tiles[st][1][r][q], &Alg[(size_t)(n0 + r) * NC + (k0) + q]);  \
                cp16(&tiles[st][2][r][q], &Wh[(o0 + r) * NC + (k0) + q]);           \
                cp16(&tiles[st][3][r][q], &Wl[(o0 + r) * NC + (k0) + q]);           \
            }                                                                       \
        } while (0)

    PROJ_LOAD(0, 0);
    CP_COMMIT();
    const int T = NC / KT;   // 8
    for (int t = 0; t < T; t++) {
        if (t + 1 < T) {
            PROJ_LOAD((t + 1) & 1, (t + 1) * KT);
            CP_COMMIT(); CP_WAIT1();
        } else CP_WAIT0();
        __syncthreads();
        int bi = t & 1;
        #pragma unroll
        for (int kk = 0; kk < KT; kk += 16) {
            uint32_t ah[4][4], al[4][4], bh[2][4], bl[2][4];
            #pragma unroll
            for (int mi = 0; mi < 4; mi++) {
                int r = wr * 64 + mi * 16 + la;
                ldsm4(ah[mi], &tiles[bi][0][r][kk + kA]);
                ldsm4(al[mi], &tiles[bi][1][r][kk + kA]);
            }
            #pragma unroll
            for (int nj = 0; nj < 2; nj++) {
                int c = wc * 32 + nj * 16 + lb;
                ldsm4(bh[nj], &tiles[bi][2][c][kk + kB]);
                ldsm4(bl[nj], &tiles[bi][3][c][kk + kB]);
            }
            #pragma unroll
            for (int mi = 0; mi < 4; mi++)
                #pragma unroll
                for (int ni = 0; ni < 4; ni++) {
                    mma16816(acc[mi][ni], ah[mi], &bh[ni >> 1][(ni & 1) * 2]);
                    mma16816(acc[mi][ni], ah[mi], &bl[ni >> 1][(ni & 1) * 2]);
                    mma16816(acc[mi][ni], al[mi], &bh[ni >> 1][(ni & 1) * 2]);
                }
        }
        __syncthreads();
    }
    #undef PROJ_LOAD

    #pragma unroll
    for (int hp = 0; hp < 2; hp++) {
        if ((wc >> 1) == hp) {
            #pragma unroll
            for (int mi = 0; mi < 4; mi++) {
                int nl = wr * 64 + mi * 16 + g;
                #pragma unroll
                for (int ni = 0; ni < 4; ni++) {
                    int ol = (wc & 1) * 32 + ni * 8 + 2 * ti;
                    tf[ol    ][nl    ] = acc[mi][ni][0];
                    tf[ol + 1][nl    ] = acc[mi][ni][1];
                    tf[ol    ][nl + 8] = acc[mi][ni][2];
                    tf[ol + 1][nl + 8] = acc[mi][ni][3];
                }
            }
        }
        __syncthreads();
        int r = tid >> 2, qn = (tid & 3) * 32;
        int o = o0 + hp * 64 + r;
        float bo = bias[o];
        size_t bse = ((size_t)b * NC + o) * NHW + n0 + qn;
        #pragma unroll
        for (int j = 0; j < 32; j += 4) {
            float4 xv = *(const float4*)&x[bse + j];
            float4 tv = *(const float4*)&tf[r][qn + j];
            float4 rv;
            rv.x = xv.x + tv.x + bo; rv.y = xv.y + tv.y + bo;
            rv.z = xv.z + tv.z + bo; rv.w = xv.w + tv.w + bo;
            *(float4*)&out[bse + j] = rv;
        }
        __syncthreads();
    }
}

// ---------------- launch ----------------
extern "C" void kernel_launch(void* const* d_in, const int* in_sizes, int n_in,
                              void* d_out, int out_size) {
    const float* x      = (const float*)d_in[0];
    const float* gns    = (const float*)d_in[1];
    const float* gnb    = (const float*)d_in[2];
    const float* wq     = (const float*)d_in[3];
    const float* bq     = (const float*)d_in[4];
    const float* wk     = (const float*)d_in[5];
    const float* bk     = (const float*)d_in[6];
    const float* wv     = (const float*)d_in[7];
    const float* bv     = (const float*)d_in[8];
    const float* wproj  = (const float*)d_in[9];
    const float* bproj  = (const float*)d_in[10];
    const float* dq     = (const float*)d_in[11];
    const float* zq     = (const float*)d_in[12];
    const float* dk     = (const float*)d_in[13];
    const float* zk     = (const float*)d_in[14];
    const float* dv     = (const float*)d_in[15];
    const float* zv     = (const float*)d_in[16];
    const float* dw     = (const float*)d_in[17];
    const float* zw     = (const float*)d_in[18];
    float* out = (float*)d_out;

    const int GSMEM = 4 * 128 * SPG * 2;     // 73728 B (gemm2)
    const int CSMEM = 2 * 4 * 128 * SP * 2;  // 81920 B (qk/proj/g1v)
    cudaFuncSetAttribute(g1v_kernel,   cudaFuncAttributeMaxDynamicSharedMemorySize, CSMEM);
    cudaFuncSetAttribute(gemm2_kernel, cudaFuncAttributeMaxDynamicSharedMemorySize, GSMEM);
    cudaFuncSetAttribute(qk_kernel,    cudaFuncAttributeMaxDynamicSharedMemorySize, CSMEM);
    cudaFuncSetAttribute(proj_kernel,  cudaFuncAttributeMaxDynamicSharedMemorySize, CSMEM);

    gn_kernel<<<NB * 32, 256>>>(x, gns, gnb);
    wsplit_kernel<<<256, 256>>>(wq, wk, wv, wproj);
    qk_kernel<<<dim3(NHW / 128, NC / 128, NB * 2), 256, CSMEM>>>(
        bq, bk, dq, zq, dk, zk);
    g1v_kernel<<<256 + NB * 32 * 32, 256, CSMEM>>>(dq, dk, bv, dv, zv);
    softmax_kernel<<<NB * NHW, 256>>>(dw, zw);
    gemm2_kernel<<<dim3(NHW / 128, NC / 128, NB), 256, GSMEM>>>(dv, dw);
    proj_kernel<<<dim3(NHW / 128, NC / 128, NB), 256, CSMEM>>>(x, bproj, out);
}

// round 16
// speedup vs baseline: 2.2476x; 1.0201x over previous
#include <cuda_runtime.h>
#include <cuda_bf16.h>
#include <cuda_fp16.h>
#include <cstdint>

#define NB 4
#define NC 256
#define NHW 4096
#define KT 32
#define SP 40    // padded smem row stride (bf16 elems) for conv kernels
#define KTG 64   // gemm1/gemm2 k-tile
#define SPG 72   // padded row stride for KTG tiles (144B, conflict-free)

// ---------------- scratch ----------------
__device__ __nv_bfloat16 g_hT_hi[NB*NHW*NC];
__device__ __nv_bfloat16 g_hT_lo[NB*NHW*NC];
__device__ __nv_bfloat16 g_w_hi[4*NC*NC];   // q,k,v,proj
__device__ __nv_bfloat16 g_w_lo[4*NC*NC];
__device__ __nv_bfloat16 g_q[NB*NHW*NC];    // quantized q codes [b][n][c]
__device__ __nv_bfloat16 g_k[NB*NHW*NC];    // quantized k codes [b][m][c]
__device__ __nv_bfloat16 g_v[NB*NC*NHW];    // quantized v codes [b][c][m]
__device__ __half        g_S[(size_t)NB*NHW*NHW];  // logits (f16)
__device__ __nv_bfloat16 g_a[(size_t)NB*NHW*NHW];  // quantized attn codes [b][n][m]
__device__ __nv_bfloat16 g_hoT_hi[NB*NHW*NC];
__device__ __nv_bfloat16 g_hoT_lo[NB*NHW*NC];

// ---------------- helpers ----------------
__device__ __forceinline__ void mma16816(float d[4], const uint32_t a[4], const uint32_t b[2]) {
    asm volatile(
        "mma.sync.aligned.m16n8k16.row.col.f32.bf16.bf16.f32 "
        "{%0,%1,%2,%3},{%4,%5,%6,%7},{%8,%9},{%0,%1,%2,%3};\n"
        : "+f"(d[0]), "+f"(d[1]), "+f"(d[2]), "+f"(d[3])
        : "r"(a[0]), "r"(a[1]), "r"(a[2]), "r"(a[3]), "r"(b[0]), "r"(b[1]));
}
__device__ __forceinline__ void ldsm4(uint32_t r[4], const void* p) {
    uint32_t a = (uint32_t)__cvta_generic_to_shared(p);
    asm volatile("ldmatrix.sync.aligned.m8n8.x4.shared.b16 {%0,%1,%2,%3},[%4];\n"
        : "=r"(r[0]), "=r"(r[1]), "=r"(r[2]), "=r"(r[3]) : "r"(a));
}
__device__ __forceinline__ void cp16(void* s, const void* g) {
    uint32_t sa = (uint32_t)__cvta_generic_to_shared(s);
    asm volatile("cp.async.cg.shared.global [%0],[%1],16;\n" :: "r"(sa), "l"(g));
}
#define CP_COMMIT() asm volatile("cp.async.commit_group;\n")
#define CP_WAIT0()  asm volatile("cp.async.wait_group 0;\n")
#define CP_WAIT1()  asm volatile("cp.async.wait_group 1;\n")

__device__ __forceinline__ float fq_code(float v, float dinv, float zp) {
    float q = rintf(v * dinv) + zp;
    q = fminf(fmaxf(q, 0.0f), 255.0f);
    return q - zp;
}

// ---------------- 1) FUSED prep: GroupNorm (blocks 0..127) + weight split (blocks 128..383) ----------------
__global__ void __launch_bounds__(256) prep_kernel(const float* __restrict__ x,
                                                   const float* __restrict__ gam,
                                                   const float* __restrict__ bet,
                                                   const float* __restrict__ wq,
                                                   const float* __restrict__ wk,
                                                   const float* __restrict__ wv,
                                                   const float* __restrict__ wp) {
    if (blockIdx.x >= 128) {
        int idx = (blockIdx.x - 128) * 256 + threadIdx.x;
        const float* ws[4] = {wq, wk, wv, wp};
        #pragma unroll
        for (int m = 0; m < 4; m++) {
            float v = ws[m][idx];
            __nv_bfloat16 hi = __float2bfloat16(v);
            g_w_hi[m * NC * NC + idx] = hi;
            g_w_lo[m * NC * NC + idx] = __float2bfloat16(v - __bfloat162float(hi));
        }
        return;
    }
    int b = blockIdx.x >> 5, gr = blockIdx.x & 31;
    const float* xp = x + ((size_t)(b * NC) + gr * 8) * NHW;
    int tid = threadIdx.x;
    const int Nf4 = 8 * NHW / 4;
    const float4* x4 = (const float4*)xp;
    float s = 0.f, ss = 0.f;
    for (int i = tid; i < Nf4; i += 256) {
        float4 v = x4[i];
        s  += v.x + v.y + v.z + v.w;
        ss += v.x * v.x + v.y * v.y + v.z * v.z + v.w * v.w;
    }
    __shared__ float rs[8], rss[8], s_sc[8], s_sh[8];
    #pragma unroll
    for (int o = 16; o; o >>= 1) {
        s  += __shfl_down_sync(0xffffffffu, s, o);
        ss += __shfl_down_sync(0xffffffffu, ss, o);
    }
    if ((tid & 31) == 0) { rs[tid >> 5] = s; rss[tid >> 5] = ss; }
    __syncthreads();
    float ts = 0.f, tss = 0.f;
    #pragma unroll
    for (int k = 0; k < 8; k++) { ts += rs[k]; tss += rss[k]; }
    const float inv = 1.0f / (float)(8 * NHW);
    float mu = ts * inv;
    float var = tss * inv - mu * mu;
    float rstd = 1.0f / sqrtf(var + 1e-6f);
    if (tid < 8) {
        float gm = gam[gr * 8 + tid];
        s_sc[tid] = gm * rstd;
        s_sh[tid] = bet[gr * 8 + tid] - mu * gm * rstd;
    }
    __syncthreads();
    __nv_bfloat16* Hh = g_hT_hi + (size_t)b * NHW * NC + gr * 8;
    __nv_bfloat16* Hl = g_hT_lo + (size_t)b * NHW * NC + gr * 8;
    for (int n = tid; n < NHW; n += 256) {
        union { __nv_bfloat16 h[8]; uint4 u; } ph, pl;
        #pragma unroll
        for (int c = 0; c < 8; c++) {
            float v = xp[(size_t)c * NHW + n] * s_sc[c] + s_sh[c];
            __nv_bfloat16 hi = __float2bfloat16(v);
            ph.h[c] = hi;
            pl.h[c] = __float2bfloat16(v - __bfloat162float(hi));
        }
        *(uint4*)&Hh[(size_t)n * NC] = ph.u;
        *(uint4*)&Hl[(size_t)n * NC] = pl.u;
    }
}

// ---------------- 2) QK conv: split-bf16 mma + quantize (double-buffered) ----------------
__global__ void __launch_bounds__(256) qk_kernel(
    const float* __restrict__ bq, const float* __restrict__ bk,
    const float* __restrict__ dqp, const float* __restrict__ zqp,
    const float* __restrict__ dkp, const float* __restrict__ zkp) {
    extern __shared__ char qsm[];
    __nv_bfloat16 (*tiles)[4][128][SP] = (__nv_bfloat16 (*)[4][128][SP])qsm;

    int z = blockIdx.z;
    int b = z >> 1, which = z & 1;
    const __nv_bfloat16* Wh = g_w_hi + which * NC * NC;
    const __nv_bfloat16* Wl = g_w_lo + which * NC * NC;
    const float* bias = which == 0 ? bq : bk;
    float d  = which == 0 ? dqp[0] : dkp[0];
    float zp = which == 0 ? zqp[0] : zkp[0];
    int n0 = blockIdx.x * 128, o0 = blockIdx.y * 128;
    const __nv_bfloat16* Ahg = g_hT_hi + (size_t)b * NHW * NC;
    const __nv_bfloat16* Alg = g_hT_lo + (size_t)b * NHW * NC;

    int tid = threadIdx.x, warp = tid >> 5, lane = tid & 31;
    int g = lane >> 2, ti = lane & 3, wr = warp & 1, wc = warp >> 1;
    int la  = lane & 15;
    int kA  = ((lane >> 4) & 1) * 8;
    int lb  = (lane & 7) + ((lane >> 4) & 1) * 8;
    int kB  = ((lane >> 3) & 1) * 8;
    float acc[4][4][4] = {};

    #define QK_LOAD(st, k0)                                                         \
        do {                                                                        \
            _Pragma("unroll")                                                       \
            for (int u = 0; u < 2; u++) {                                           \
                int c = tid + u * 256; int r = c >> 2, q = (c & 3) * 8;             \
                cp16(&tiles[st][0][r][q], &Ahg[(size_t)(n0 + r) * NC + (k0) + q]);  \
                cp16(&tiles[st][1][r][q], &Alg[(size_t)(n0 + r) * NC + (k0) + q]);  \
                cp16(&tiles[st][2][r][q], &Wh[(o0 + r) * NC + (k0) + q]);           \
                cp16(&tiles[st][3][r][q], &Wl[(o0 + r) * NC + (k0) + q]);           \
            }                                                                       \
        } while (0)

    QK_LOAD(0, 0);
    CP_COMMIT();
    const int T = NC / KT;   // 8
    for (int t = 0; t < T; t++) {
        if (t + 1 < T) {
            QK_LOAD((t + 1) & 1, (t + 1) * KT);
            CP_COMMIT(); CP_WAIT1();
        } else CP_WAIT0();
        __syncthreads();
        int bi = t & 1;
        #pragma unroll
        for (int kk = 0; kk < KT; kk += 16) {
            uint32_t ah[4][4], al[4][4], bh[2][4], bl[2][4];
            #pragma unroll
            for (int mi = 0; mi < 4; mi++) {
                int r = wr * 64 + mi * 16 + la;
                ldsm4(ah[mi], &tiles[bi][0][r][kk + kA]);
                ldsm4(al[mi], &tiles[bi][1][r][kk + kA]);
            }
            #pragma unroll
            for (int nj = 0; nj < 2; nj++) {
                int c = wc * 32 + nj * 16 + lb;
                ldsm4(bh[nj], &tiles[bi][2][c][kk + kB]);
                ldsm4(bl[nj], &tiles[bi][3][c][kk + kB]);
            }
            #pragma unroll
            for (int mi = 0; mi < 4; mi++)
                #pragma unroll
                for (int ni = 0; ni < 4; ni++) {
                    mma16816(acc[mi][ni], ah[mi], &bh[ni >> 1][(ni & 1) * 2]);
                    mma16816(acc[mi][ni], ah[mi], &bl[ni >> 1][(ni & 1) * 2]);
                    mma16816(acc[mi][ni], al[mi], &bh[ni >> 1][(ni & 1) * 2]);
                }
        }
        __syncthreads();
    }
    #undef QK_LOAD

    float dinv = 1.0f / d;
    __nv_bfloat16* Out = (which == 0 ? g_q : g_k) + (size_t)b * NHW * NC;
    #pragma unroll
    for (int mi = 0; mi < 4; mi++) {
        int n = n0 + wr * 64 + mi * 16 + g;
        #pragma unroll
        for (int ni = 0; ni < 4; ni++) {
            int o = o0 + wc * 32 + ni * 8 + 2 * ti;
            float b0 = bias[o], b1 = bias[o + 1];
            union { __nv_bfloat16 h[2]; uint32_t u; } p0, p1;
            p0.h[0] = __float2bfloat16(fq_code(acc[mi][ni][0] + b0, dinv, zp));
            p0.h[1] = __float2bfloat16(fq_code(acc[mi][ni][1] + b1, dinv, zp));
            p1.h[0] = __float2bfloat16(fq_code(acc[mi][ni][2] + b0, dinv, zp));
            p1.h[1] = __float2bfloat16(fq_code(acc[mi][ni][3] + b1, dinv, zp));
            *(uint32_t*)&Out[(size_t)n * NC + o]       = p0.u;
            *(uint32_t*)&Out[(size_t)(n + 8) * NC + o] = p1.u;
        }
    }
}

// ---------------- 3) FUSED: v-conv (first 256 blocks) + gemm1 (next 4096, 3-stage) ----------------
__global__ void __launch_bounds__(256) g1v_kernel(
    const float* __restrict__ dqp, const float* __restrict__ dkp,
    const float* __restrict__ bv, const float* __restrict__ dvp,
    const float* __restrict__ zvp) {
    extern __shared__ char dsmc[];
    int bid = blockIdx.x;
    int tid = threadIdx.x, warp = tid >> 5, lane = tid & 31;
    int g = lane >> 2, ti = lane & 3, wr = warp & 1, wc = warp >> 1;
    int la  = lane & 15;
    int kA  = ((lane >> 4) & 1) * 8;
    int lb  = (lane & 7) + ((lane >> 4) & 1) * 8;
    int kB  = ((lane >> 3) & 1) * 8;

    if (bid < 256) {
        // ---- v-conv body (split-bf16, 2-stage) ----
        __nv_bfloat16 (*tiles)[4][128][SP] = (__nv_bfloat16 (*)[4][128][SP])dsmc;
        __nv_bfloat16 (*tb)[136] = (__nv_bfloat16 (*)[136])dsmc;
        int n0 = (bid & 31) * 128;
        int o0 = ((bid >> 5) & 1) * 128;
        int b  = bid >> 6;
        const __nv_bfloat16* Wh = g_w_hi + 2 * NC * NC;
        const __nv_bfloat16* Wl = g_w_lo + 2 * NC * NC;
        const __nv_bfloat16* Ahg = g_hT_hi + (size_t)b * NHW * NC;
        const __nv_bfloat16* Alg = g_hT_lo + (size_t)b * NHW * NC;
        float d = dvp[0], zp = zvp[0];
        float acc[4][4][4] = {};

        #define V_LOAD(st, k0)                                                          \
            do {                                                                        \
                _Pragma("unroll")                                                       \
                for (int u = 0; u < 2; u++) {                                           \
                    int c = tid + u * 256; int r = c >> 2, q = (c & 3) * 8;             \
                    cp16(&tiles[st][0][r][q], &Ahg[(size_t)(n0 + r) * NC + (k0) + q]);  \
                    cp16(&tiles[st][1][r][q], &Alg[(size_t)(n0 + r) * NC + (k0) + q]);  \
                    cp16(&tiles[st][2][r][q], &Wh[(o0 + r) * NC + (k0) + q]);           \
                    cp16(&tiles[st][3][r][q], &Wl[(o0 + r) * NC + (k0) + q]);           \
                }                                                                       \
            } while (0)

        V_LOAD(0, 0);
        CP_COMMIT();
        const int T = NC / KT;   // 8
        for (int t = 0; t < T; t++) {
            if (t + 1 < T) {
                V_LOAD((t + 1) & 1, (t + 1) * KT);
                CP_COMMIT(); CP_WAIT1();
            } else CP_WAIT0();
            __syncthreads();
            int bi = t & 1;
            #pragma unroll
            for (int kk = 0; kk < KT; kk += 16) {
                uint32_t ah[4][4], al[4][4], bh[2][4], bl[2][4];
                #pragma unroll
                for (int mi = 0; mi < 4; mi++) {
                    int r = wr * 64 + mi * 16 + la;
                    ldsm4(ah[mi], &tiles[bi][0][r][kk + kA]);
                    ldsm4(al[mi], &tiles[bi][1][r][kk + kA]);
                }
                #pragma unroll
                for (int nj = 0; nj < 2; nj++) {
                    int c = wc * 32 + nj * 16 + lb;
                    ldsm4(bh[nj], &tiles[bi][2][c][kk + kB]);
                    ldsm4(bl[nj], &tiles[bi][3][c][kk + kB]);
                }
                #pragma unroll
                for (int mi = 0; mi < 4; mi++)
                    #pragma unroll
                    for (int ni = 0; ni < 4; ni++) {
                        mma16816(acc[mi][ni], ah[mi], &bh[ni >> 1][(ni & 1) * 2]);
                        mma16816(acc[mi][ni], ah[mi], &bl[ni >> 1][(ni & 1) * 2]);
                        mma16816(acc[mi][ni], al[mi], &bh[ni >> 1][(ni & 1) * 2]);
                    }
            }
            __syncthreads();
        }
        #undef V_LOAD

        float dinv = 1.0f / d;
        #pragma unroll
        for (int mi = 0; mi < 4; mi++) {
            int nl = wr * 64 + mi * 16 + g;
            #pragma unroll
            for (int ni = 0; ni < 4; ni++) {
                int ol = wc * 32 + ni * 8 + 2 * ti;
                float b0 = bv[o0 + ol], b1 = bv[o0 + ol + 1];
                tb[ol    ][nl    ] = __float2bfloat16(fq_code(acc[mi][ni][0] + b0, dinv, zp));
                tb[ol + 1][nl    ] = __float2bfloat16(fq_code(acc[mi][ni][1] + b1, dinv, zp));
                tb[ol    ][nl + 8] = __float2bfloat16(fq_code(acc[mi][ni][2] + b0, dinv, zp));
                tb[ol + 1][nl + 8] = __float2bfloat16(fq_code(acc[mi][ni][3] + b1, dinv, zp));
            }
        }
        __syncthreads();
        int r = tid >> 1, half = (tid & 1) * 64;
        #pragma unroll
        for (int j = 0; j < 64; j += 8)
            *(uint4*)&g_v[((size_t)b * NC + o0 + r) * NHW + n0 + half + j] =
                *(uint4*)&tb[r][half + j];
    } else {
        // ---- gemm1 body: S = q . k^T (KTG=64, 3-stage, one barrier/iter) ----
        int gid = bid - 256;
        int m0 = (gid & 31) * 128;
        int n0 = ((gid >> 5) & 31) * 128;
        int b  = gid >> 10;
        __nv_bfloat16 (*As)[128][SPG] = (__nv_bfloat16 (*)[128][SPG])dsmc;
        __nv_bfloat16 (*Bs)[128][SPG] = (__nv_bfloat16 (*)[128][SPG])(dsmc + 3 * 128 * SPG * 2);
        const __nv_bfloat16* A  = g_q + (size_t)b * NHW * NC;
        const __nv_bfloat16* Bm = g_k + (size_t)b * NHW * NC;
        float acc[4][4][4] = {};
        #define G1_LOAD(st, k0)                                                     \
            do {                                                                    \
                _Pragma("unroll")                                                   \
                for (int u = 0; u < 4; u++) {                                       \
                    int c = tid + u * 256; int r = c >> 3, q = (c & 7) * 8;         \
                    cp16(&As[st][r][q], &A [(size_t)(n0 + r) * NC + (k0) + q]);     \
                    cp16(&Bs[st][r][q], &Bm[(size_t)(m0 + r) * NC + (k0) + q]);     \
                }                                                                   \
            } while (0)
        G1_LOAD(0, 0);
        CP_COMMIT();
        G1_LOAD(1, KTG);
        CP_COMMIT();
        const int T = NC / KTG;   // 4
        int st = 0;
        for (int t = 0; t < T; t++) {
            if (t + 1 < T) CP_WAIT1(); else CP_WAIT0();
            __syncthreads();
            if (t + 2 < T) {
                int st2 = st + 2; if (st2 >= 3) st2 -= 3;
                G1_LOAD(st2, (t + 2) * KTG);
                CP_COMMIT();
            }
            #pragma unroll
            for (int kk = 0; kk < KTG; kk += 16) {
                uint32_t af[4][4], bf[2][4];
                #pragma unroll
                for (int mi = 0; mi < 4; mi++)
                    ldsm4(af[mi], &As[st][wr * 64 + mi * 16 + la][kk + kA]);
                #pragma unroll
                for (int nj = 0; nj < 2; nj++)
                    ldsm4(bf[nj], &Bs[st][wc * 32 + nj * 16 + lb][kk + kB]);
                #pragma unroll
                for (int mi = 0; mi < 4; mi++)
                    #pragma unroll
                    for (int ni = 0; ni < 4; ni++)
                        mma16816(acc[mi][ni], af[mi], &bf[ni >> 1][(ni & 1) * 2]);
            }
            if (++st >= 3) st = 0;
        }
        #undef G1_LOAD
        float sc = dqp[0] * dkp[0] * 0.0625f;
        __half* Sp = g_S + (size_t)b * NHW * NHW;
        #pragma unroll
        for (int mi = 0; mi < 4; mi++) {
            int n = n0 + wr * 64 + mi * 16 + g;
            #pragma unroll
            for (int ni = 0; ni < 4; ni++) {
                int m = m0 + wc * 32 + ni * 8 + 2 * ti;
                *(__half2*)&Sp[(size_t)n * NHW + m] =
                    __floats2half2_rn(acc[mi][ni][0] * sc, acc[mi][ni][1] * sc);
                *(__half2*)&Sp[(size_t)(n + 8) * NHW + m] =
                    __floats2half2_rn(acc[mi][ni][2] * sc, acc[mi][ni][3] * sc);
            }
        }
    }
}

// ---------------- 4) softmax + 8-bit quantize (f16 in, bf16 codes out) ----------------
__global__ void __launch_bounds__(256) softmax_kernel(const float* __restrict__ dwp,
                                                      const float* __restrict__ zwp) {
    size_t row = blockIdx.x;
    const __half* s = g_S + row * NHW;
    __nv_bfloat16* a = g_a + row * NHW;
    int tid = threadIdx.x;
    float v[16];
    #pragma unroll
    for (int j = 0; j < 2; j++) {
        uint4 t = *(const uint4*)&s[(j * 256 + tid) * 8];
        const __half2* hp = (const __half2*)&t;
        #pragma unroll
        for (int l = 0; l < 4; l++) {
            float2 f = __half22float2(hp[l]);
            v[j * 8 + 2 * l]     = f.x;
            v[j * 8 + 2 * l + 1] = f.y;
        }
    }
    float mx = -3.4e38f;
    #pragma unroll
    for (int i = 0; i < 16; i++) mx = fmaxf(mx, v[i]);
    __shared__ float red[8];
    #pragma unroll
    for (int o = 16; o; o >>= 1) mx = fmaxf(mx, __shfl_xor_sync(0xffffffffu, mx, o));
    if ((tid & 31) == 0) red[tid >> 5] = mx;
    __syncthreads();
    mx = red[0];
    #pragma unroll
    for (int k = 1; k < 8; k++) mx = fmaxf(mx, red[k]);
    __syncthreads();
    float sum = 0.f;
    #pragma unroll
    for (int i = 0; i < 16; i++) { v[i] = __expf(v[i] - mx); sum += v[i]; }
    #pragma unroll
    for (int o = 16; o; o >>= 1) sum += __shfl_xor_sync(0xffffffffu, sum, o);
    if ((tid & 31) == 0) red[tid >> 5] = sum;
    __syncthreads();
    sum = 0.f;
    #pragma unroll
    for (int k = 0; k < 8; k++) sum += red[k];
    float rinv = 1.0f / sum;
    float dinv = 1.0f / dwp[0], zw = zwp[0];
    #pragma unroll
    for (int j = 0; j < 2; j++) {
        union { __nv_bfloat16 h[8]; uint4 u; } pk;
        #pragma unroll
        for (int l = 0; l < 8; l++)
            pk.h[l] = __float2bfloat16(fq_code(v[j * 8 + l] * rinv, dinv, zw));
        *(uint4*)&a[(j * 256 + tid) * 8] = pk.u;
    }
}

// ---------------- 5) gemm2: hoT = a . v^T (128x128, KTG=64, 3-stage) ----------------
__global__ void __launch_bounds__(256) gemm2_kernel(const float* __restrict__ dvp,
                                                    const float* __restrict__ dwp) {
    extern __shared__ __nv_bfloat16 ds[];
    __nv_bfloat16 (*As)[128][SPG] = (__nv_bfloat16 (*)[128][SPG])ds;
    __nv_bfloat16 (*Bs)[128][SPG] = (__nv_bfloat16 (*)[128][SPG])(ds + 3 * 128 * SPG);

    int b = blockIdx.z, n0 = blockIdx.x * 128, c0 = blockIdx.y * 128;
    const __nv_bfloat16* A  = g_a + (size_t)b * NHW * NHW;   // [n][m]
    const __nv_bfloat16* Bm = g_v + (size_t)b * NC * NHW;    // [c][m]
    int tid = threadIdx.x, warp = tid >> 5, lane = tid & 31;
    int g = lane >> 2, ti = lane & 3, wr = warp & 1, wc = warp >> 1;
    int la  = lane & 15;
    int kA  = ((lane >> 4) & 1) * 8;
    int lb  = (lane & 7) + ((lane >> 4) & 1) * 8;
    int kB  = ((lane >> 3) & 1) * 8;
    float acc[4][4][4] = {};
    #define G2_LOAD(st, k0)                                                     \
        do {                                                                    \
            _Pragma("unroll")                                                   \
            for (int u = 0; u < 4; u++) {                                       \
                int c = tid + u * 256; int r = c >> 3, q = (c & 7) * 8;         \
                cp16(&As[st][r][q], &A [(size_t)(n0 + r) * NHW + (k0) + q]);    \
                cp16(&Bs[st][r][q], &Bm[(size_t)(c0 + r) * NHW + (k0) + q]);    \
            }                                                                   \
        } while (0)
    G2_LOAD(0, 0);
    CP_COMMIT();
    G2_LOAD(1, KTG);
    CP_COMMIT();
    const int T = NHW / KTG;  // 64
    int st = 0;
    for (int t = 0; t < T; t++) {
        if (t + 1 < T) CP_WAIT1(); else CP_WAIT0();
        __syncthreads();
        if (t + 2 < T) {
            int st2 = st + 2; if (st2 >= 3) st2 -= 3;
            G2_LOAD(st2, (t + 2) * KTG);
            CP_COMMIT();
        }
        #pragma unroll
        for (int kk = 0; kk < KTG; kk += 16) {
            uint32_t af[4][4], bf[2][4];
            #pragma unroll
            for (int mi = 0; mi < 4; mi++)
                ldsm4(af[mi], &As[st][wr * 64 + mi * 16 + la][kk + kA]);
            #pragma unroll
            for (int nj = 0; nj < 2; nj++)
                ldsm4(bf[nj], &Bs[st][wc * 32 + nj * 16 + lb][kk + kB]);
            #pragma unroll
            for (int mi = 0; mi < 4; mi++)
                #pragma unroll
                for (int ni = 0; ni < 4; ni++)
                    mma16816(acc[mi][ni], af[mi], &bf[ni >> 1][(ni & 1) * 2]);
        }
        if (++st >= 3) st = 0;
    }
    #undef G2_LOAD
    float sc = dvp[0] * dwp[0];
    __nv_bfloat16* Oh = g_hoT_hi + (size_t)b * NHW * NC;
    __nv_bfloat16* Ol = g_hoT_lo + (size_t)b * NHW * NC;
    #pragma unroll
    for (int mi = 0; mi < 4; mi++) {
        int n = n0 + wr * 64 + mi * 16 + g;
        #pragma unroll
        for (int ni = 0; ni < 4; ni++) {
            int c = c0 + wc * 32 + ni * 8 + 2 * ti;
            #pragma unroll
            for (int half = 0; half < 2; half++) {
                float v0 = acc[mi][ni][2 * half] * sc;
                float v1 = acc[mi][ni][2 * half + 1] * sc;
                __nv_bfloat16 h0 = __float2bfloat16(v0);
                __nv_bfloat16 h1 = __float2bfloat16(v1);
                union { __nv_bfloat16 h[2]; uint32_t u; } ph, pl;
                ph.h[0] = h0; ph.h[1] = h1;
                pl.h[0] = __float2bfloat16(v0 - __bfloat162float(h0));
                pl.h[1] = __float2bfloat16(v1 - __bfloat162float(h1));
                size_t off = (size_t)(n + 8 * half) * NC + c;
                *(uint32_t*)&Oh[off] = ph.u;
                *(uint32_t*)&Ol[off] = pl.u;
            }
        }
    }
}

// ---------------- 6) proj: split-bf16 mma + bias + residual (double-buffered) ----------------
__global__ void __launch_bounds__(256) proj_kernel(const float* __restrict__ x,
                                                   const float* __restrict__ bias,
                                                   float* __restrict__ out) {
    extern __shared__ char qsm[];
    __nv_bfloat16 (*tiles)[4][128][SP] = (__nv_bfloat16 (*)[4][128][SP])qsm;
    float (*tf)[132] = (float (*)[132])qsm;

    int b = blockIdx.z;
    int n0 = blockIdx.x * 128, o0 = blockIdx.y * 128;
    const __nv_bfloat16* Wh = g_w_hi + 3 * NC * NC;
    const __nv_bfloat16* Wl = g_w_lo + 3 * NC * NC;
    const __nv_bfloat16* Ahg = g_hoT_hi + (size_t)b * NHW * NC;
    const __nv_bfloat16* Alg = g_hoT_lo + (size_t)b * NHW * NC;

    int tid = threadIdx.x, warp = tid >> 5, lane = tid & 31;
    int g = lane >> 2, ti = lane & 3, wr = warp & 1, wc = warp >> 1;
    int la  = lane & 15;
    int kA  = ((lane >> 4) & 1) * 8;
    int lb  = (lane & 7) + ((lane >> 4) & 1) * 8;
    int kB  = ((lane >> 3) & 1) * 8;
    float acc[4][4][4] = {};

    #define PROJ_LOAD(st, k0)                                                       \
        do {                                                                        \
            _Pragma("unroll")                                                       \
            for (int u = 0; u < 2; u++) {                                           \
                int c = tid + u * 256; int r = c >> 2, q = (c & 3) * 8;             \
                cp16(&tiles[st][0][r][q], &Ahg[(size_t)(n0 + r) * NC + (k0) + q]);  \
                cp16(&tiles[st][1][r][q], &Alg[(size_t)(n0 + r) * NC + (k0) + q]);  \
                cp16(&tiles[st][2][r][q], &Wh[(o0 + r) * NC + (k0) + q]);           \
                cp16(&tiles[st][3][r][q], &Wl[(o0 + r) * NC + (k0) + q]);           \
            }                                                                       \
        } while (0)

    PROJ_LOAD(0, 0);
    CP_COMMIT();
    const int T = NC / KT;   // 8
    for (int t = 0; t < T; t++) {
        if (t + 1 < T) {
            PROJ_LOAD((t + 1) & 1, (t + 1) * KT);
            CP_COMMIT(); CP_WAIT1();
        } else CP_WAIT0();
        __syncthreads();
        int bi = t & 1;
        #pragma unroll
        for (int kk = 0; kk < KT; kk += 16) {
            uint32_t ah[4][4], al[4][4], bh[2][4], bl[2][4];
            #pragma unroll
            for (int mi = 0; mi < 4; mi++) {
                int r = wr * 64 + mi * 16 + la;
                ldsm4(ah[mi], &tiles[bi][0][r][kk + kA]);
                ldsm4(al[mi], &tiles[bi][1][r][kk + kA]);
            }
            #pragma unroll
            for (int nj = 0; nj < 2; nj++) {
                int c = wc * 32 + nj * 16 + lb;
                ldsm4(bh[nj], &tiles[bi][2][c][kk + kB]);
                ldsm4(bl[nj], &tiles[bi][3][c][kk + kB]);
            }
            #pragma unroll
            for (int mi = 0; mi < 4; mi++)
                #pragma unroll
                for (int ni = 0; ni < 4; ni++) {
                    mma16816(acc[mi][ni], ah[mi], &bh[ni >> 1][(ni & 1) * 2]);
                    mma16816(acc[mi][ni], ah[mi], &bl[ni >> 1][(ni & 1) * 2]);
                    mma16816(acc[mi][ni], al[mi], &bh[ni >> 1][(ni & 1) * 2]);
                }
        }
        __syncthreads();
    }
    #undef PROJ_LOAD

    #pragma unroll
    for (int hp = 0; hp < 2; hp++) {
        if ((wc >> 1) == hp) {
            #pragma unroll
            for (int mi = 0; mi < 4; mi++) {
                int nl = wr * 64 + mi * 16 + g;
                #pragma unroll
                for (int ni = 0; ni < 4; ni++) {
                    int ol = (wc & 1) * 32 + ni * 8 + 2 * ti;
                    tf[ol    ][nl    ] = acc[mi][ni][0];
                    tf[ol + 1][nl    ] = acc[mi][ni][1];
                    tf[ol    ][nl + 8] = acc[mi][ni][2];
                    tf[ol + 1][nl + 8] = acc[mi][ni][3];
                }
            }
        }
        __syncthreads();
        int r = tid >> 2, qn = (tid & 3) * 32;
        int o = o0 + hp * 64 + r;
        float bo = bias[o];
        size_t bse = ((size_t)b * NC + o) * NHW + n0 + qn;
        #pragma unroll
        for (int j = 0; j < 32; j += 4) {
            float4 xv = *(const float4*)&x[bse + j];
            float4 tv = *(const float4*)&tf[r][qn + j];
            float4 rv;
            rv.x = xv.x + tv.x + bo; rv.y = xv.y + tv.y + bo;
            rv.z = xv.z + tv.z + bo; rv.w = xv.w + tv.w + bo;
            *(float4*)&out[bse + j] = rv;
        }
        __syncthreads();
    }
}

// ---------------- launch ----------------
extern "C" void kernel_launch(void* const* d_in, const int* in_sizes, int n_in,
                              void* d_out, int out_size) {
    const float* x      = (const float*)d_in[0];
    const float* gns    = (const float*)d_in[1];
    const float* gnb    = (const float*)d_in[2];
    const float* wq     = (const float*)d_in[3];
    const float* bq     = (const float*)d_in[4];
    const float* wk     = (const float*)d_in[5];
    const float* bk     = (const float*)d_in[6];
    const float* wv     = (const float*)d_in[7];
    const float* bv     = (const float*)d_in[8];
    const float* wproj  = (const float*)d_in[9];
    const float* bproj  = (const float*)d_in[10];
    const float* dq     = (const float*)d_in[11];
    const float* zq     = (const float*)d_in[12];
    const float* dk     = (const float*)d_in[13];
    const float* zk     = (const float*)d_in[14];
    const float* dv     = (const float*)d_in[15];
    const float* zv     = (const float*)d_in[16];
    const float* dw     = (const float*)d_in[17];
    const float* zw     = (const float*)d_in[18];
    float* out = (float*)d_out;

    const int GSMEM = 2 * 3 * 128 * SPG * 2;  // 110592 B (gemm2, g1v: 3-stage)
    const int CSMEM = 2 * 4 * 128 * SP * 2;   // 81920 B (qk/proj: 2-stage)
    cudaFuncSetAttribute(g1v_kernel,   cudaFuncAttributeMaxDynamicSharedMemorySize, GSMEM);
    cudaFuncSetAttribute(gemm2_kernel, cudaFuncAttributeMaxDynamicSharedMemorySize, GSMEM);
    cudaFuncSetAttribute(qk_kernel,    cudaFuncAttributeMaxDynamicSharedMemorySize, CSMEM);
    cudaFuncSetAttribute(proj_kernel,  cudaFuncAttributeMaxDynamicSharedMemorySize, CSMEM);

    prep_kernel<<<128 + 256, 256>>>(x, gns, gnb, wq, wk, wv, wproj);
    qk_kernel<<<dim3(NHW / 128, NC / 128, NB * 2), 256, CSMEM>>>(
        bq, bk, dq, zq, dk, zk);
    g1v_kernel<<<256 + NB * 32 * 32, 256, GSMEM>>>(dq, dk, bv, dv, zv);
    softmax_kernel<<<NB * NHW, 256>>>(dw, zw);
    gemm2_kernel<<<dim3(NHW / 128, NC / 128, NB), 256, GSMEM>>>(dv, dw);
    proj_kernel<<<dim3(NHW / 128, NC / 128, NB), 256, CSMEM>>>(x, bproj, out);
}